// round 10
// baseline (speedup 1.0000x reference)
#include <cuda_runtime.h>
#include <cuda_bf16.h>
#include <cstdint>
#include <math.h>

#define B_ 4
#define L_ 256
#define D_ 512
#define H_ 8
#define DK_ 64

typedef __nv_bfloat16 bf16;
typedef __nv_bfloat162 bf162;

// ---------------------------------------------------------------------------
// Scratch (allocation-free rule: __device__ globals)
// ---------------------------------------------------------------------------
__device__ float g_qh[B_*H_*L_*DK_];
__device__ float g_kh[B_*H_*L_*DK_];
__device__ float g_vh[B_*H_*L_*DK_];

__device__ __align__(16) bf16 g_Xhi[3*1024*512];   // q,k,v inputs [m][k]
__device__ __align__(16) bf16 g_Xlo[3*1024*512];
__device__ __align__(16) bf16 g_Whi[4*512*512];    // Wq,Wk,Wv,W0 TRANSPOSED [n][k]
__device__ __align__(16) bf16 g_Wlo[4*512*512];
__device__ __align__(16) bf16 g_ctx_hi[1024*512];  // attention context [m][k]
__device__ __align__(16) bf16 g_ctx_lo[1024*512];

// ---------------------------------------------------------------------------
__device__ __forceinline__ uint32_t smem_u32(const void* p) {
    uint32_t a;
    asm("{ .reg .u64 t; cvta.to.shared.u64 t, %1; cvt.u32.u64 %0, t; }" : "=r"(a) : "l"(p));
    return a;
}
__device__ __forceinline__ float tanh_fast(float x) {
    float y;
    asm("tanh.approx.f32 %0, %1;" : "=f"(y) : "f"(x));
    return y;
}
__device__ __forceinline__ void ldm_x4(uint32_t* r, uint32_t addr) {
    asm volatile("ldmatrix.sync.aligned.m8n8.x4.shared.b16 {%0,%1,%2,%3}, [%4];"
        : "=r"(r[0]), "=r"(r[1]), "=r"(r[2]), "=r"(r[3]) : "r"(addr));
}
__device__ __forceinline__ void mma_bf16(float* c, const uint32_t* a, const uint32_t* b) {
    asm volatile(
        "mma.sync.aligned.m16n8k16.row.col.f32.bf16.bf16.f32 "
        "{%0,%1,%2,%3}, {%4,%5,%6,%7}, {%8,%9}, {%0,%1,%2,%3};"
        : "+f"(c[0]), "+f"(c[1]), "+f"(c[2]), "+f"(c[3])
        : "r"(a[0]), "r"(a[1]), "r"(a[2]), "r"(a[3]), "r"(b[0]), "r"(b[1]));
}
__device__ __forceinline__ void split_bf(float x, bf16& hi, bf16& lo) {
    hi = __float2bfloat16_rn(x);
    lo = __float2bfloat16_rn(x - __bfloat162float(hi));
}

// ---------------------------------------------------------------------------
// One-time fp32 -> (hi,lo) bf16 converts
// ---------------------------------------------------------------------------
__global__ __launch_bounds__(256) void convert_x_kernel(
    const float* __restrict__ q, const float* __restrict__ k, const float* __restrict__ v)
{
    int z = blockIdx.y;
    const float* src = (z == 0) ? q : (z == 1 ? k : v);
    int i = (blockIdx.x * 256 + threadIdx.x) * 4;
    float4 x = *(const float4*)(src + i);
    bf16 h0, l0, h1, l1, h2, l2, h3, l3;
    split_bf(x.x, h0, l0); split_bf(x.y, h1, l1);
    split_bf(x.z, h2, l2); split_bf(x.w, h3, l3);
    size_t base = (size_t)z * (1024*512) + i;
    bf162* ph = (bf162*)&g_Xhi[base];
    bf162* pl = (bf162*)&g_Xlo[base];
    ph[0] = bf162(h0, h1); ph[1] = bf162(h2, h3);
    pl[0] = bf162(l0, l1); pl[1] = bf162(l2, l3);
}

__global__ __launch_bounds__(256) void convert_w_kernel(
    const float* __restrict__ Wq, const float* __restrict__ Wk,
    const float* __restrict__ Wv, const float* __restrict__ W0)
{
    __shared__ float tile[32][33];
    int z = blockIdx.z;
    const float* W = (z == 0) ? Wq : (z == 1 ? Wk : (z == 2 ? Wv : W0));
    int k0 = blockIdx.x * 32, n0 = blockIdx.y * 32;
    int tx = threadIdx.x, ty = threadIdx.y;
    #pragma unroll
    for (int it = 0; it < 4; it++)
        tile[ty + it * 8][tx] = W[(size_t)(k0 + ty + it * 8) * D_ + n0 + tx];
    __syncthreads();
    size_t zb = (size_t)z * (512*512);
    #pragma unroll
    for (int it = 0; it < 4; it++) {
        int nr = ty + it * 8;
        bf16 hi, lo;
        split_bf(tile[tx][nr], hi, lo);
        g_Whi[zb + (size_t)(n0 + nr) * D_ + k0 + tx] = hi;
        g_Wlo[zb + (size_t)(n0 + nr) * D_ + k0 + tx] = lo;
    }
}

// ---------------------------------------------------------------------------
// 3xBF16 tensor-core GEMM (unchanged from R7 winner)
// ---------------------------------------------------------------------------
#define SA 40
#define A_HALVES (128*SA)
#define B_HALVES (64*SA)
#define GEMM_BUF_H (2*A_HALVES + 2*B_HALVES)
#define GEMM_SMEM_BYTES (2*GEMM_BUF_H*2)

template<bool HEADSPLIT>
__device__ __forceinline__ void gemm_core(
    const bf16* __restrict__ Ahi_g, const bf16* __restrict__ Alo_g,
    const bf16* __restrict__ Bhi_g, const bf16* __restrict__ Blo_g,
    const float* __restrict__ bias, float* __restrict__ Y)
{
    extern __shared__ __align__(16) bf16 smh[];
    const int tid = threadIdx.x;
    const int lane = tid & 31, wid = tid >> 5;
    const int g = lane >> 2, t4 = lane & 3;
    const int warp_m = (wid & 3) * 32;
    const int warp_n = (wid >> 2) * 32;
    const int m0 = blockIdx.x * 128, n0 = blockIdx.y * 64;

    const int am = tid >> 1, ah = (tid & 1) * 16;
    const int bn = tid >> 2, bh = (tid & 3) * 8;
    const bf16* Asrc_h = Ahi_g + (size_t)(m0 + am) * D_ + ah;
    const bf16* Asrc_l = Alo_g + (size_t)(m0 + am) * D_ + ah;
    const bf16* Bsrc_h = Bhi_g + (size_t)(n0 + bn) * D_ + bh;
    const bf16* Bsrc_l = Blo_g + (size_t)(n0 + bn) * D_ + bh;

    float acc[2][4][4];
    #pragma unroll
    for (int i = 0; i < 2; i++)
        #pragma unroll
        for (int j = 0; j < 4; j++)
            #pragma unroll
            for (int c = 0; c < 4; c++) acc[i][j][c] = 0.0f;

    const int lrow = lane & 15;
    const int lk   = (lane >> 4) * 8;
    const int bln  = lane & 7;
    const int bseg = (lane >> 3) & 1;
    const int bhi16 = (lane >> 4);
    const uint32_t smem_base = smem_u32(smh);
    const uint32_t aoff0 = ((warp_m + lrow)      * SA + lk) * 2;
    const uint32_t aoff1 = ((warp_m + 16 + lrow) * SA + lk) * 2;
    const uint32_t boff0 = ((warp_n + bln)       * SA + bseg * 8) * 2 + bhi16 * (8 * SA * 2);
    const uint32_t boff1 = boff0 + 16 * SA * 2;

    uint4 rAh0, rAh1, rAl0, rAl1, rBh, rBl;
    rAh0 = *(const uint4*)(Asrc_h);  rAh1 = *(const uint4*)(Asrc_h + 8);
    rAl0 = *(const uint4*)(Asrc_l);  rAl1 = *(const uint4*)(Asrc_l + 8);
    rBh  = *(const uint4*)(Bsrc_h);  rBl  = *(const uint4*)(Bsrc_l);

    for (int s = 0; s < 16; s++) {
        const int buf = s & 1;
        bf16* Ah_s = smh + buf * GEMM_BUF_H;
        bf16* Al_s = Ah_s + A_HALVES;
        bf16* Bh_s = Al_s + A_HALVES;
        bf16* Bl_s = Bh_s + B_HALVES;

        *(uint4*)&Ah_s[am * SA + ah]     = rAh0;
        *(uint4*)&Ah_s[am * SA + ah + 8] = rAh1;
        *(uint4*)&Al_s[am * SA + ah]     = rAl0;
        *(uint4*)&Al_s[am * SA + ah + 8] = rAl1;
        *(uint4*)&Bh_s[bn * SA + bh] = rBh;
        *(uint4*)&Bl_s[bn * SA + bh] = rBl;
        __syncthreads();

        if (s < 15) {
            const int off = (s + 1) * 32;
            rAh0 = *(const uint4*)(Asrc_h + off); rAh1 = *(const uint4*)(Asrc_h + off + 8);
            rAl0 = *(const uint4*)(Asrc_l + off); rAl1 = *(const uint4*)(Asrc_l + off + 8);
            rBh  = *(const uint4*)(Bsrc_h + off); rBl  = *(const uint4*)(Bsrc_l + off);
        }

        const uint32_t base = smem_base + (uint32_t)(buf * GEMM_BUF_H * 2);
        const uint32_t aBh = base;
        const uint32_t aBl = base + A_HALVES * 2;
        const uint32_t bBh = base + 2 * A_HALVES * 2;
        const uint32_t bBl = bBh + B_HALVES * 2;

        #pragma unroll
        for (int kk = 0; kk < 2; kk++) {
            const uint32_t ko = kk * 32;
            uint32_t Ah0[4], Ah1[4], Al0[4], Al1[4];
            uint32_t Bh0[4], Bh1[4], Bl0[4], Bl1[4];
            ldm_x4(Ah0, aBh + aoff0 + ko);
            ldm_x4(Ah1, aBh + aoff1 + ko);
            ldm_x4(Al0, aBl + aoff0 + ko);
            ldm_x4(Al1, aBl + aoff1 + ko);
            ldm_x4(Bh0, bBh + boff0 + ko);
            ldm_x4(Bh1, bBh + boff1 + ko);
            ldm_x4(Bl0, bBl + boff0 + ko);
            ldm_x4(Bl1, bBl + boff1 + ko);

            #pragma unroll
            for (int i = 0; i < 2; i++) {
                uint32_t* ahp = i ? Ah1 : Ah0;
                uint32_t* alp = i ? Al1 : Al0;
                #pragma unroll
                for (int j = 0; j < 4; j++) {
                    uint32_t* bhp = (j < 2) ? Bh0 : Bh1;
                    uint32_t* blp = (j < 2) ? Bl0 : Bl1;
                    uint32_t bhf[2] = { bhp[(j & 1) * 2], bhp[(j & 1) * 2 + 1] };
                    uint32_t blf[2] = { blp[(j & 1) * 2], blp[(j & 1) * 2 + 1] };
                    mma_bf16(acc[i][j], ahp, bhf);
                    mma_bf16(acc[i][j], ahp, blf);
                    mma_bf16(acc[i][j], alp, bhf);
                }
            }
        }
    }

    #pragma unroll
    for (int i = 0; i < 2; i++) {
        #pragma unroll
        for (int j = 0; j < 4; j++) {
            int col_loc = warp_n + (j >> 1) * 16 + (j & 1) * 8 + 2 * t4;
            int cng = n0 + col_loc;
            float b0 = bias[cng], b1 = bias[cng + 1];
            int r0 = m0 + warp_m + i * 16 + g;
            int r1 = r0 + 8;
            float2 v0 = make_float2(acc[i][j][0] + b0, acc[i][j][1] + b1);
            float2 v1 = make_float2(acc[i][j][2] + b0, acc[i][j][3] + b1);
            if (HEADSPLIT) {
                int h = blockIdx.y;
                float* d0 = Y + ((size_t)((r0 >> 8) * H_ + h) * L_ + (r0 & 255)) * DK_ + col_loc;
                float* d1 = Y + ((size_t)((r1 >> 8) * H_ + h) * L_ + (r1 & 255)) * DK_ + col_loc;
                *(float2*)d0 = v0;
                *(float2*)d1 = v1;
            } else {
                *(float2*)(Y + (size_t)r0 * D_ + cng) = v0;
                *(float2*)(Y + (size_t)r1 * D_ + cng) = v1;
            }
        }
    }
}

__global__ __launch_bounds__(256, 2) void qkv_mma_kernel(
    const float* __restrict__ bq, const float* __restrict__ bk, const float* __restrict__ bv)
{
    int z = blockIdx.z;
    const float* bias = (z == 0) ? bq : (z == 1 ? bk : bv);
    float* out = (z == 0) ? g_qh : (z == 1 ? g_kh : g_vh);
    gemm_core<true>(g_Xhi + (size_t)z * (1024*512), g_Xlo + (size_t)z * (1024*512),
                    g_Whi + (size_t)z * (512*512),  g_Wlo + (size_t)z * (512*512),
                    bias, out);
}

__global__ __launch_bounds__(256, 2) void out_mma_kernel(
    const float* __restrict__ b0, float* __restrict__ Y)
{
    gemm_core<false>(g_ctx_hi, g_ctx_lo,
                     g_Whi + (size_t)3 * (512*512), g_Wlo + (size_t)3 * (512*512),
                     b0, Y);
}

// ---------------------------------------------------------------------------
// Fused Bahdanau attention v3 — MUFU-density layout (KS_ST fixed to 68 for
// 16B-aligned float4 reads at every d).
// CTA = (b, h, 32-row i-block): grid (8, 32) = 256 CTAs, 256 threads.
// ---------------------------------------------------------------------------
#define IB 32
#define QS_ST 34
#define KS_ST 68
#define S_ST 260
#define ATTN_SMEM_FLOATS (64*QS_ST + 64*KS_ST + IB*S_ST + 64 + IB)
#define ATTN_SMEM_BYTES  (ATTN_SMEM_FLOATS * 4)

__global__ __launch_bounds__(256) void attn_kernel(
    const int* __restrict__ mask, const float* __restrict__ vp)
{
    extern __shared__ __align__(16) float sm[];
    float* Qs   = sm;                    // [d][i]  64 x 34
    float* Ks   = Qs + 64 * QS_ST;       // [d][j]  64 x 68
    float* S    = Ks + 64 * KS_ST;       // [i][j]  32 x 260
    float* vps  = S + IB * S_ST;         // 64
    float* rinv = vps + 64;              // 32

    const int tid = threadIdx.x;
    const int bh = blockIdx.y;
    const int b = bh >> 3;
    const int h = bh & 7;
    const int i0 = blockIdx.x * IB;

    const float* qh  = g_qh + (size_t)(bh * L_ + i0) * DK_;
    const float* khp = g_kh + (size_t)bh * L_ * DK_;
    const float* vhp = g_vh + (size_t)bh * L_ * DK_;

    if (tid < 64) vps[tid] = vp[h * DK_ + tid];

    // Q transposed: thread (i = tid>>3, d0 = (tid&7)*8)
    {
        int i = tid >> 3, d0 = (tid & 7) * 8;
        float4 t0 = *(const float4*)&qh[(size_t)i * DK_ + d0];
        float4 t1 = *(const float4*)&qh[(size_t)i * DK_ + d0 + 4];
        Qs[(d0 + 0) * QS_ST + i] = t0.x; Qs[(d0 + 1) * QS_ST + i] = t0.y;
        Qs[(d0 + 2) * QS_ST + i] = t0.z; Qs[(d0 + 3) * QS_ST + i] = t0.w;
        Qs[(d0 + 4) * QS_ST + i] = t1.x; Qs[(d0 + 5) * QS_ST + i] = t1.y;
        Qs[(d0 + 6) * QS_ST + i] = t1.z; Qs[(d0 + 7) * QS_ST + i] = t1.w;
    }

    const int il = tid & 31;   // score row (conflict-free LDS across lanes)
    const int jg = tid >> 5;   // warp-uniform j-group: 8 j's (broadcast LDS)

    // ---- Scores: per j-tile of 64 ----
    for (int jb = 0; jb < 4; jb++) {
        __syncthreads();   // prev-tile consumers done (1st iter: Q/vps visible)
        {
            int j = tid >> 2, d0 = (tid & 3) * 16;
            const float* kr = khp + (size_t)(jb * 64 + j) * DK_;
            #pragma unroll
            for (int u = 0; u < 4; u++) {
                float4 t = *(const float4*)&kr[d0 + u * 4];
                Ks[(d0 + u * 4 + 0) * KS_ST + j] = t.x;
                Ks[(d0 + u * 4 + 1) * KS_ST + j] = t.y;
                Ks[(d0 + u * 4 + 2) * KS_ST + j] = t.z;
                Ks[(d0 + u * 4 + 3) * KS_ST + j] = t.w;
            }
        }
        __syncthreads();

        float acc[8] = {};
        #pragma unroll 2
        for (int d = 0; d < 64; d++) {
            float w  = vps[d];
            float qv = Qs[d * QS_ST + il];
            float4 k0 = *(const float4*)&Ks[d * KS_ST + jg * 8];
            float4 k1 = *(const float4*)&Ks[d * KS_ST + jg * 8 + 4];
            acc[0] += w * tanh_fast(qv + k0.x);
            acc[1] += w * tanh_fast(qv + k0.y);
            acc[2] += w * tanh_fast(qv + k0.z);
            acc[3] += w * tanh_fast(qv + k0.w);
            acc[4] += w * tanh_fast(qv + k1.x);
            acc[5] += w * tanh_fast(qv + k1.y);
            acc[6] += w * tanh_fast(qv + k1.z);
            acc[7] += w * tanh_fast(qv + k1.w);
        }
        float* srow = &S[il * S_ST + jb * 64 + jg * 8];
        *(float4*)srow       = make_float4(acc[0], acc[1], acc[2], acc[3]);
        *(float4*)(srow + 4) = make_float4(acc[4], acc[5], acc[6], acc[7]);
    }
    __syncthreads();

    // ---- Masked exp + rowsum (no max subtraction; |s| <= sum|vp| ~ 6) ----
    {
        int warp = tid >> 5, lane = tid & 31;
        #pragma unroll
        for (int r = 0; r < 4; r++) {
            int row = warp * 4 + r;
            const int* mrow = mask + ((size_t)b * L_ + i0 + row) * L_;
            float sum = 0.0f;
            #pragma unroll
            for (int c8 = 0; c8 < 8; c8++) {
                int c = c8 * 32 + lane;
                float s = S[row * S_ST + c];
                float e = (mrow[c] == 0) ? 0.0f : __expf(s);
                S[row * S_ST + c] = e;
                sum += e;
            }
            #pragma unroll
            for (int off = 16; off > 0; off >>= 1)
                sum += __shfl_xor_sync(0xFFFFFFFFu, sum, off);
            if (lane == 0) rinv[row] = 1.0f / sum;
        }
    }
    __syncthreads();

    // ---- PV: i = tid>>3 (32 rows), 8 dk per thread; V via L1 ----
    {
        int i = tid >> 3, dk0 = (tid & 7) * 8;
        const float* Vg = vhp + dk0;
        float o[8] = {};
        const float* Srow = &S[i * S_ST];
        #pragma unroll 4
        for (int j = 0; j < L_; j++) {
            float p = Srow[j];
            float4 v0 = *(const float4*)(Vg + (size_t)j * DK_);
            float4 v1 = *(const float4*)(Vg + (size_t)j * DK_ + 4);
            o[0] += p * v0.x; o[1] += p * v0.y; o[2] += p * v0.z; o[3] += p * v0.w;
            o[4] += p * v1.x; o[5] += p * v1.y; o[6] += p * v1.z; o[7] += p * v1.w;
        }
        float inv = rinv[i];
        size_t off = ((size_t)(b * L_ + i0 + i)) * D_ + h * DK_ + dk0;
        bf162* ph = (bf162*)&g_ctx_hi[off];
        bf162* pl = (bf162*)&g_ctx_lo[off];
        #pragma unroll
        for (int u = 0; u < 4; u++) {
            float va = o[u * 2] * inv, vb = o[u * 2 + 1] * inv;
            bf16 ha, la, hb, lb;
            split_bf(va, ha, la);
            split_bf(vb, hb, lb);
            ph[u] = bf162(ha, hb);
            pl[u] = bf162(la, lb);
        }
    }
}

// ===========================================================================
extern "C" void kernel_launch(void* const* d_in, const int* in_sizes, int n_in,
                              void* d_out, int out_size)
{
    const float* q    = (const float*)d_in[0];
    const float* k    = (const float*)d_in[1];
    const float* v    = (const float*)d_in[2];
    const int*   mask = (const int*)  d_in[3];
    const float* Wq   = (const float*)d_in[4];
    const float* bq   = (const float*)d_in[5];
    const float* Wk   = (const float*)d_in[6];
    const float* bk   = (const float*)d_in[7];
    const float* Wv   = (const float*)d_in[8];
    const float* bv   = (const float*)d_in[9];
    const float* vp   = (const float*)d_in[10];
    const float* W0   = (const float*)d_in[11];
    const float* b0   = (const float*)d_in[12];
    float* out = (float*)d_out;

    static bool attr_set = false;
    if (!attr_set) {
        cudaFuncSetAttribute(attn_kernel,
                             cudaFuncAttributeMaxDynamicSharedMemorySize, ATTN_SMEM_BYTES);
        cudaFuncSetAttribute(qkv_mma_kernel,
                             cudaFuncAttributeMaxDynamicSharedMemorySize, GEMM_SMEM_BYTES);
        cudaFuncSetAttribute(out_mma_kernel,
                             cudaFuncAttributeMaxDynamicSharedMemorySize, GEMM_SMEM_BYTES);
        attr_set = true;
    }

    convert_x_kernel<<<dim3(512, 3), 256>>>(q, k, v);
    convert_w_kernel<<<dim3(16, 16, 4), dim3(32, 8)>>>(Wq, Wk, Wv, W0);
    qkv_mma_kernel<<<dim3(8, 8, 3), 256, GEMM_SMEM_BYTES>>>(bq, bk, bv);
    attn_kernel<<<dim3(8, 32), 256, ATTN_SMEM_BYTES>>>(mask, vp);
    out_mma_kernel<<<dim3(8, 8), 256, GEMM_SMEM_BYTES>>>(b0, out);
}

// round 11
// speedup vs baseline: 1.1330x; 1.1330x over previous
#include <cuda_runtime.h>
#include <cuda_bf16.h>
#include <cstdint>
#include <math.h>

#define B_ 4
#define L_ 256
#define D_ 512
#define H_ 8
#define DK_ 64

typedef __nv_bfloat16 bf16;
typedef __nv_bfloat162 bf162;

// ---------------------------------------------------------------------------
// Scratch (allocation-free rule: __device__ globals)
// ---------------------------------------------------------------------------
__device__ float g_qh[B_*H_*L_*DK_];
__device__ float g_kh[B_*H_*L_*DK_];
__device__ float g_vh[B_*H_*L_*DK_];
__device__ float g_S[B_*H_*L_*L_];                 // masked exp(scores), 8MB

__device__ __align__(16) bf16 g_Xhi[3*1024*512];   // q,k,v inputs [m][k]
__device__ __align__(16) bf16 g_Xlo[3*1024*512];
__device__ __align__(16) bf16 g_Whi[4*512*512];    // Wq,Wk,Wv,W0 TRANSPOSED [n][k]
__device__ __align__(16) bf16 g_Wlo[4*512*512];
__device__ __align__(16) bf16 g_ctx_hi[1024*512];  // attention context [m][k]
__device__ __align__(16) bf16 g_ctx_lo[1024*512];

// ---------------------------------------------------------------------------
__device__ __forceinline__ uint32_t smem_u32(const void* p) {
    uint32_t a;
    asm("{ .reg .u64 t; cvta.to.shared.u64 t, %1; cvt.u32.u64 %0, t; }" : "=r"(a) : "l"(p));
    return a;
}
__device__ __forceinline__ float tanh_fast(float x) {
    float y;
    asm("tanh.approx.f32 %0, %1;" : "=f"(y) : "f"(x));
    return y;
}
__device__ __forceinline__ void ldm_x4(uint32_t* r, uint32_t addr) {
    asm volatile("ldmatrix.sync.aligned.m8n8.x4.shared.b16 {%0,%1,%2,%3}, [%4];"
        : "=r"(r[0]), "=r"(r[1]), "=r"(r[2]), "=r"(r[3]) : "r"(addr));
}
__device__ __forceinline__ void mma_bf16(float* c, const uint32_t* a, const uint32_t* b) {
    asm volatile(
        "mma.sync.aligned.m16n8k16.row.col.f32.bf16.bf16.f32 "
        "{%0,%1,%2,%3}, {%4,%5,%6,%7}, {%8,%9}, {%0,%1,%2,%3};"
        : "+f"(c[0]), "+f"(c[1]), "+f"(c[2]), "+f"(c[3])
        : "r"(a[0]), "r"(a[1]), "r"(a[2]), "r"(a[3]), "r"(b[0]), "r"(b[1]));
}
__device__ __forceinline__ void split_bf(float x, bf16& hi, bf16& lo) {
    hi = __float2bfloat16_rn(x);
    lo = __float2bfloat16_rn(x - __bfloat162float(hi));
}

// ---------------------------------------------------------------------------
// One-time fp32 -> (hi,lo) bf16 converts
// ---------------------------------------------------------------------------
__global__ __launch_bounds__(256) void convert_x_kernel(
    const float* __restrict__ q, const float* __restrict__ k, const float* __restrict__ v)
{
    int z = blockIdx.y;
    const float* src = (z == 0) ? q : (z == 1 ? k : v);
    int i = (blockIdx.x * 256 + threadIdx.x) * 4;
    float4 x = *(const float4*)(src + i);
    bf16 h0, l0, h1, l1, h2, l2, h3, l3;
    split_bf(x.x, h0, l0); split_bf(x.y, h1, l1);
    split_bf(x.z, h2, l2); split_bf(x.w, h3, l3);
    size_t base = (size_t)z * (1024*512) + i;
    bf162* ph = (bf162*)&g_Xhi[base];
    bf162* pl = (bf162*)&g_Xlo[base];
    ph[0] = bf162(h0, h1); ph[1] = bf162(h2, h3);
    pl[0] = bf162(l0, l1); pl[1] = bf162(l2, l3);
}

__global__ __launch_bounds__(256) void convert_w_kernel(
    const float* __restrict__ Wq, const float* __restrict__ Wk,
    const float* __restrict__ Wv, const float* __restrict__ W0)
{
    __shared__ float tile[32][33];
    int z = blockIdx.z;
    const float* W = (z == 0) ? Wq : (z == 1 ? Wk : (z == 2 ? Wv : W0));
    int k0 = blockIdx.x * 32, n0 = blockIdx.y * 32;
    int tx = threadIdx.x, ty = threadIdx.y;
    #pragma unroll
    for (int it = 0; it < 4; it++)
        tile[ty + it * 8][tx] = W[(size_t)(k0 + ty + it * 8) * D_ + n0 + tx];
    __syncthreads();
    size_t zb = (size_t)z * (512*512);
    #pragma unroll
    for (int it = 0; it < 4; it++) {
        int nr = ty + it * 8;
        bf16 hi, lo;
        split_bf(tile[tx][nr], hi, lo);
        g_Whi[zb + (size_t)(n0 + nr) * D_ + k0 + tx] = hi;
        g_Wlo[zb + (size_t)(n0 + nr) * D_ + k0 + tx] = lo;
    }
}

// ---------------------------------------------------------------------------
// 3xBF16 tensor-core GEMM (unchanged from R7 winner)
// ---------------------------------------------------------------------------
#define SA 40
#define A_HALVES (128*SA)
#define B_HALVES (64*SA)
#define GEMM_BUF_H (2*A_HALVES + 2*B_HALVES)
#define GEMM_SMEM_BYTES (2*GEMM_BUF_H*2)

template<bool HEADSPLIT>
__device__ __forceinline__ void gemm_core(
    const bf16* __restrict__ Ahi_g, const bf16* __restrict__ Alo_g,
    const bf16* __restrict__ Bhi_g, const bf16* __restrict__ Blo_g,
    const float* __restrict__ bias, float* __restrict__ Y)
{
    extern __shared__ __align__(16) bf16 smh[];
    const int tid = threadIdx.x;
    const int lane = tid & 31, wid = tid >> 5;
    const int g = lane >> 2, t4 = lane & 3;
    const int warp_m = (wid & 3) * 32;
    const int warp_n = (wid >> 2) * 32;
    const int m0 = blockIdx.x * 128, n0 = blockIdx.y * 64;

    const int am = tid >> 1, ah = (tid & 1) * 16;
    const int bn = tid >> 2, bh = (tid & 3) * 8;
    const bf16* Asrc_h = Ahi_g + (size_t)(m0 + am) * D_ + ah;
    const bf16* Asrc_l = Alo_g + (size_t)(m0 + am) * D_ + ah;
    const bf16* Bsrc_h = Bhi_g + (size_t)(n0 + bn) * D_ + bh;
    const bf16* Bsrc_l = Blo_g + (size_t)(n0 + bn) * D_ + bh;

    float acc[2][4][4];
    #pragma unroll
    for (int i = 0; i < 2; i++)
        #pragma unroll
        for (int j = 0; j < 4; j++)
            #pragma unroll
            for (int c = 0; c < 4; c++) acc[i][j][c] = 0.0f;

    const int lrow = lane & 15;
    const int lk   = (lane >> 4) * 8;
    const int bln  = lane & 7;
    const int bseg = (lane >> 3) & 1;
    const int bhi16 = (lane >> 4);
    const uint32_t smem_base = smem_u32(smh);
    const uint32_t aoff0 = ((warp_m + lrow)      * SA + lk) * 2;
    const uint32_t aoff1 = ((warp_m + 16 + lrow) * SA + lk) * 2;
    const uint32_t boff0 = ((warp_n + bln)       * SA + bseg * 8) * 2 + bhi16 * (8 * SA * 2);
    const uint32_t boff1 = boff0 + 16 * SA * 2;

    uint4 rAh0, rAh1, rAl0, rAl1, rBh, rBl;
    rAh0 = *(const uint4*)(Asrc_h);  rAh1 = *(const uint4*)(Asrc_h + 8);
    rAl0 = *(const uint4*)(Asrc_l);  rAl1 = *(const uint4*)(Asrc_l + 8);
    rBh  = *(const uint4*)(Bsrc_h);  rBl  = *(const uint4*)(Bsrc_l);

    for (int s = 0; s < 16; s++) {
        const int buf = s & 1;
        bf16* Ah_s = smh + buf * GEMM_BUF_H;
        bf16* Al_s = Ah_s + A_HALVES;
        bf16* Bh_s = Al_s + A_HALVES;
        bf16* Bl_s = Bh_s + B_HALVES;

        *(uint4*)&Ah_s[am * SA + ah]     = rAh0;
        *(uint4*)&Ah_s[am * SA + ah + 8] = rAh1;
        *(uint4*)&Al_s[am * SA + ah]     = rAl0;
        *(uint4*)&Al_s[am * SA + ah + 8] = rAl1;
        *(uint4*)&Bh_s[bn * SA + bh] = rBh;
        *(uint4*)&Bl_s[bn * SA + bh] = rBl;
        __syncthreads();

        if (s < 15) {
            const int off = (s + 1) * 32;
            rAh0 = *(const uint4*)(Asrc_h + off); rAh1 = *(const uint4*)(Asrc_h + off + 8);
            rAl0 = *(const uint4*)(Asrc_l + off); rAl1 = *(const uint4*)(Asrc_l + off + 8);
            rBh  = *(const uint4*)(Bsrc_h + off); rBl  = *(const uint4*)(Bsrc_l + off);
        }

        const uint32_t base = smem_base + (uint32_t)(buf * GEMM_BUF_H * 2);
        const uint32_t aBh = base;
        const uint32_t aBl = base + A_HALVES * 2;
        const uint32_t bBh = base + 2 * A_HALVES * 2;
        const uint32_t bBl = bBh + B_HALVES * 2;

        #pragma unroll
        for (int kk = 0; kk < 2; kk++) {
            const uint32_t ko = kk * 32;
            uint32_t Ah0[4], Ah1[4], Al0[4], Al1[4];
            uint32_t Bh0[4], Bh1[4], Bl0[4], Bl1[4];
            ldm_x4(Ah0, aBh + aoff0 + ko);
            ldm_x4(Ah1, aBh + aoff1 + ko);
            ldm_x4(Al0, aBl + aoff0 + ko);
            ldm_x4(Al1, aBl + aoff1 + ko);
            ldm_x4(Bh0, bBh + boff0 + ko);
            ldm_x4(Bh1, bBh + boff1 + ko);
            ldm_x4(Bl0, bBl + boff0 + ko);
            ldm_x4(Bl1, bBl + boff1 + ko);

            #pragma unroll
            for (int i = 0; i < 2; i++) {
                uint32_t* ahp = i ? Ah1 : Ah0;
                uint32_t* alp = i ? Al1 : Al0;
                #pragma unroll
                for (int j = 0; j < 4; j++) {
                    uint32_t* bhp = (j < 2) ? Bh0 : Bh1;
                    uint32_t* blp = (j < 2) ? Bl0 : Bl1;
                    uint32_t bhf[2] = { bhp[(j & 1) * 2], bhp[(j & 1) * 2 + 1] };
                    uint32_t blf[2] = { blp[(j & 1) * 2], blp[(j & 1) * 2 + 1] };
                    mma_bf16(acc[i][j], ahp, bhf);
                    mma_bf16(acc[i][j], ahp, blf);
                    mma_bf16(acc[i][j], alp, bhf);
                }
            }
        }
    }

    #pragma unroll
    for (int i = 0; i < 2; i++) {
        #pragma unroll
        for (int j = 0; j < 4; j++) {
            int col_loc = warp_n + (j >> 1) * 16 + (j & 1) * 8 + 2 * t4;
            int cng = n0 + col_loc;
            float b0 = bias[cng], b1 = bias[cng + 1];
            int r0 = m0 + warp_m + i * 16 + g;
            int r1 = r0 + 8;
            float2 v0 = make_float2(acc[i][j][0] + b0, acc[i][j][1] + b1);
            float2 v1 = make_float2(acc[i][j][2] + b0, acc[i][j][3] + b1);
            if (HEADSPLIT) {
                int h = blockIdx.y;
                float* d0 = Y + ((size_t)((r0 >> 8) * H_ + h) * L_ + (r0 & 255)) * DK_ + col_loc;
                float* d1 = Y + ((size_t)((r1 >> 8) * H_ + h) * L_ + (r1 & 255)) * DK_ + col_loc;
                *(float2*)d0 = v0;
                *(float2*)d1 = v1;
            } else {
                *(float2*)(Y + (size_t)r0 * D_ + cng) = v0;
                *(float2*)(Y + (size_t)r1 * D_ + cng) = v1;
            }
        }
    }
}

__global__ __launch_bounds__(256, 2) void qkv_mma_kernel(
    const float* __restrict__ bq, const float* __restrict__ bk, const float* __restrict__ bv)
{
    int z = blockIdx.z;
    const float* bias = (z == 0) ? bq : (z == 1 ? bk : bv);
    float* out = (z == 0) ? g_qh : (z == 1 ? g_kh : g_vh);
    gemm_core<true>(g_Xhi + (size_t)z * (1024*512), g_Xlo + (size_t)z * (1024*512),
                    g_Whi + (size_t)z * (512*512),  g_Wlo + (size_t)z * (512*512),
                    bias, out);
}

__global__ __launch_bounds__(256, 2) void out_mma_kernel(
    const float* __restrict__ b0, float* __restrict__ Y)
{
    gemm_core<false>(g_ctx_hi, g_ctx_lo,
                     g_Whi + (size_t)3 * (512*512), g_Wlo + (size_t)3 * (512*512),
                     b0, Y);
}

// ---------------------------------------------------------------------------
// Scores kernel: E[bh][i][j] = mask ? exp(sum_d vp[d]*tanh(q+k)) : 0
// grid (4, 4, 32) = 512 CTAs x 256 thr; smem ~35KB -> 6 CTAs/SM (48 warps).
// Thread computes a 4x4 (i,j) tile; ti=tid>>4 (row group), tj=tid&15 (col
// group) so global writes are coalesced.
// ---------------------------------------------------------------------------
#define SC_ST 68

__global__ __launch_bounds__(256) void scores_kernel(
    const int* __restrict__ mask, const float* __restrict__ vp)
{
    __shared__ float Qs[64 * SC_ST];
    __shared__ float Ks[64 * SC_ST];
    __shared__ float vps[64];

    const int tid = threadIdx.x;
    const int bh = blockIdx.z;
    const int b = bh >> 3, h = bh & 7;
    const int i0 = blockIdx.x * 64, j0 = blockIdx.y * 64;

    const float* qh = g_qh + (size_t)(bh * L_ + i0) * DK_;
    const float* kh = g_kh + (size_t)(bh * L_ + j0) * DK_;

    if (tid < 64) vps[tid] = vp[h * DK_ + tid];
    {
        int r = tid >> 2, d0 = (tid & 3) * 16;
        #pragma unroll
        for (int u = 0; u < 4; u++) {
            float4 tq = *(const float4*)&qh[(size_t)r * DK_ + d0 + u * 4];
            Qs[(d0 + u * 4 + 0) * SC_ST + r] = tq.x;
            Qs[(d0 + u * 4 + 1) * SC_ST + r] = tq.y;
            Qs[(d0 + u * 4 + 2) * SC_ST + r] = tq.z;
            Qs[(d0 + u * 4 + 3) * SC_ST + r] = tq.w;
            float4 tk = *(const float4*)&kh[(size_t)r * DK_ + d0 + u * 4];
            Ks[(d0 + u * 4 + 0) * SC_ST + r] = tk.x;
            Ks[(d0 + u * 4 + 1) * SC_ST + r] = tk.y;
            Ks[(d0 + u * 4 + 2) * SC_ST + r] = tk.z;
            Ks[(d0 + u * 4 + 3) * SC_ST + r] = tk.w;
        }
    }
    __syncthreads();

    const int ti = tid >> 4;   // i group (warp-broadcast Q reads)
    const int tj = tid & 15;   // j group (coalesced writes)

    float acc[4][4] = {};
    #pragma unroll 2
    for (int d = 0; d < 64; d++) {
        float w = vps[d];
        float4 qv = *(const float4*)&Qs[d * SC_ST + ti * 4];
        float4 kv = *(const float4*)&Ks[d * SC_ST + tj * 4];
        float qa[4] = {qv.x, qv.y, qv.z, qv.w};
        float kb[4] = {kv.x, kv.y, kv.z, kv.w};
        #pragma unroll
        for (int a = 0; a < 4; a++)
            #pragma unroll
            for (int c = 0; c < 4; c++)
                acc[a][c] += w * tanh_fast(qa[a] + kb[c]);
    }

    // mask + exp (no max-pass: |s| <= sum|vp| ~ 6, exp safe in fp32) + store
    float* Sg = g_S + (size_t)bh * (L_ * L_);
    #pragma unroll
    for (int a = 0; a < 4; a++) {
        int row = i0 + ti * 4 + a;
        const int4 m = *(const int4*)(mask + ((size_t)b * L_ + row) * L_ + j0 + tj * 4);
        float4 e;
        e.x = m.x ? __expf(acc[a][0]) : 0.0f;
        e.y = m.y ? __expf(acc[a][1]) : 0.0f;
        e.z = m.z ? __expf(acc[a][2]) : 0.0f;
        e.w = m.w ? __expf(acc[a][3]) : 0.0f;
        *(float4*)&Sg[(size_t)row * L_ + j0 + tj * 4] = e;
    }
}

// ---------------------------------------------------------------------------
// PV kernel: out[i][dk] = sum_j E[i][j] V[j][dk] / sum_j E[i][j]
// grid (8, 32) = 256 CTAs x 256 thr; smem 50.7KB -> 4 CTAs/SM.
// Per-thread redundant rowsum (no reductions). V tiled 64 rows at a time.
// ---------------------------------------------------------------------------
#define ES_ST 260
#define VS_ST 68
#define PV_SMEM_BYTES ((32*ES_ST + 64*VS_ST) * 4)

__global__ __launch_bounds__(256) void pv_kernel()
{
    extern __shared__ __align__(16) float psm[];
    float* Es = psm;              // [i][j] 32 x 260
    float* Vs = Es + 32 * ES_ST;  // [j][dk] 64 x 68

    const int tid = threadIdx.x;
    const int bh = blockIdx.y;
    const int b = bh >> 3, h = bh & 7;
    const int i0 = blockIdx.x * 32;

    const float* Sg = g_S + (size_t)bh * (L_ * L_) + (size_t)i0 * L_;
    const float* vhp = g_vh + (size_t)bh * L_ * DK_;

    // Load E tile (32 x 256), coalesced
    for (int t = tid; t < 32 * 64; t += 256) {
        int r = t >> 6, c = (t & 63) * 4;
        *(float4*)&Es[r * ES_ST + c] = *(const float4*)&Sg[(size_t)r * L_ + c];
    }

    const int i = tid >> 3, dk0 = (tid & 7) * 8;
    float o[8] = {};
    float sum = 0.0f;

    for (int jb = 0; jb < 4; jb++) {
        __syncthreads();   // prev Vs consumers done; first iter: Es visible
        {
            int r = tid >> 2, d0 = (tid & 3) * 16;
            const float* vr = vhp + (size_t)(jb * 64 + r) * DK_ + d0;
            #pragma unroll
            for (int u = 0; u < 4; u++)
                *(float4*)&Vs[r * VS_ST + d0 + u * 4] = *(const float4*)(vr + u * 4);
        }
        __syncthreads();

        const float* Erow = &Es[i * ES_ST + jb * 64];
        #pragma unroll 4
        for (int j = 0; j < 64; j++) {
            float p = Erow[j];
            sum += p;
            float4 v0 = *(const float4*)&Vs[j * VS_ST + dk0];
            float4 v1 = *(const float4*)&Vs[j * VS_ST + dk0 + 4];
            o[0] += p * v0.x; o[1] += p * v0.y; o[2] += p * v0.z; o[3] += p * v0.w;
            o[4] += p * v1.x; o[5] += p * v1.y; o[6] += p * v1.z; o[7] += p * v1.w;
        }
    }

    float inv = 1.0f / sum;
    size_t off = ((size_t)(b * L_ + i0 + i)) * D_ + h * DK_ + dk0;
    bf162* ph = (bf162*)&g_ctx_hi[off];
    bf162* pl = (bf162*)&g_ctx_lo[off];
    #pragma unroll
    for (int u = 0; u < 4; u++) {
        float va = o[u * 2] * inv, vb = o[u * 2 + 1] * inv;
        bf16 ha, la, hb, lb;
        split_bf(va, ha, la);
        split_bf(vb, hb, lb);
        ph[u] = bf162(ha, hb);
        pl[u] = bf162(la, lb);
    }
}

// ===========================================================================
extern "C" void kernel_launch(void* const* d_in, const int* in_sizes, int n_in,
                              void* d_out, int out_size)
{
    const float* q    = (const float*)d_in[0];
    const float* k    = (const float*)d_in[1];
    const float* v    = (const float*)d_in[2];
    const int*   mask = (const int*)  d_in[3];
    const float* Wq   = (const float*)d_in[4];
    const float* bq   = (const float*)d_in[5];
    const float* Wk   = (const float*)d_in[6];
    const float* bk   = (const float*)d_in[7];
    const float* Wv   = (const float*)d_in[8];
    const float* bv   = (const float*)d_in[9];
    const float* vp   = (const float*)d_in[10];
    const float* W0   = (const float*)d_in[11];
    const float* b0   = (const float*)d_in[12];
    float* out = (float*)d_out;

    static bool attr_set = false;
    if (!attr_set) {
        cudaFuncSetAttribute(qkv_mma_kernel,
                             cudaFuncAttributeMaxDynamicSharedMemorySize, GEMM_SMEM_BYTES);
        cudaFuncSetAttribute(out_mma_kernel,
                             cudaFuncAttributeMaxDynamicSharedMemorySize, GEMM_SMEM_BYTES);
        cudaFuncSetAttribute(pv_kernel,
                             cudaFuncAttributeMaxDynamicSharedMemorySize, PV_SMEM_BYTES);
        attr_set = true;
    }

    convert_x_kernel<<<dim3(512, 3), 256>>>(q, k, v);
    convert_w_kernel<<<dim3(16, 16, 4), dim3(32, 8)>>>(Wq, Wk, Wv, W0);
    qkv_mma_kernel<<<dim3(8, 8, 3), 256, GEMM_SMEM_BYTES>>>(bq, bk, bv);
    scores_kernel<<<dim3(4, 4, 32), 256>>>(mask, vp);
    pv_kernel<<<dim3(8, 32), 256, PV_SMEM_BYTES>>>();
    out_mma_kernel<<<dim3(8, 8), 256, GEMM_SMEM_BYTES>>>(b0, out);
}

// round 12
// speedup vs baseline: 1.3133x; 1.1591x over previous
#include <cuda_runtime.h>
#include <cuda_bf16.h>
#include <cstdint>
#include <math.h>

#define B_ 4
#define L_ 256
#define D_ 512
#define H_ 8
#define DK_ 64

typedef __nv_bfloat16 bf16;
typedef __nv_bfloat162 bf162;

// ---------------------------------------------------------------------------
// Scratch (allocation-free rule: __device__ globals)
// ---------------------------------------------------------------------------
__device__ float g_qh[B_*H_*L_*DK_];
__device__ float g_kh[B_*H_*L_*DK_];
__device__ float g_vh[B_*H_*L_*DK_];
__device__ float g_rinv[B_*H_*L_];                  // 1/rowsum

__device__ __align__(16) bf16 g_Ehi[B_*H_*L_*L_];   // exp(scores) hi, 4MB
__device__ __align__(16) bf16 g_Elo[B_*H_*L_*L_];   // exp(scores) lo, 4MB
__device__ __align__(16) bf16 g_VThi[B_*H_*DK_*L_]; // V^T [bh][dk][j]
__device__ __align__(16) bf16 g_VTlo[B_*H_*DK_*L_];

__device__ __align__(16) bf16 g_Xhi[3*1024*512];   // q,k,v inputs [m][k]
__device__ __align__(16) bf16 g_Xlo[3*1024*512];
__device__ __align__(16) bf16 g_Whi[4*512*512];    // Wq,Wk,Wv,W0 TRANSPOSED [n][k]
__device__ __align__(16) bf16 g_Wlo[4*512*512];
__device__ __align__(16) bf16 g_ctx_hi[1024*512];  // attention context [m][k]
__device__ __align__(16) bf16 g_ctx_lo[1024*512];

// ---------------------------------------------------------------------------
__device__ __forceinline__ uint32_t smem_u32(const void* p) {
    uint32_t a;
    asm("{ .reg .u64 t; cvta.to.shared.u64 t, %1; cvt.u32.u64 %0, t; }" : "=r"(a) : "l"(p));
    return a;
}
__device__ __forceinline__ float tanh_fast(float x) {
    float y;
    asm("tanh.approx.f32 %0, %1;" : "=f"(y) : "f"(x));
    return y;
}
__device__ __forceinline__ void ldm_x4(uint32_t* r, uint32_t addr) {
    asm volatile("ldmatrix.sync.aligned.m8n8.x4.shared.b16 {%0,%1,%2,%3}, [%4];"
        : "=r"(r[0]), "=r"(r[1]), "=r"(r[2]), "=r"(r[3]) : "r"(addr));
}
__device__ __forceinline__ void mma_bf16(float* c, const uint32_t* a, const uint32_t* b) {
    asm volatile(
        "mma.sync.aligned.m16n8k16.row.col.f32.bf16.bf16.f32 "
        "{%0,%1,%2,%3}, {%4,%5,%6,%7}, {%8,%9}, {%0,%1,%2,%3};"
        : "+f"(c[0]), "+f"(c[1]), "+f"(c[2]), "+f"(c[3])
        : "r"(a[0]), "r"(a[1]), "r"(a[2]), "r"(a[3]), "r"(b[0]), "r"(b[1]));
}
__device__ __forceinline__ void split_bf(float x, bf16& hi, bf16& lo) {
    hi = __float2bfloat16_rn(x);
    lo = __float2bfloat16_rn(x - __bfloat162float(hi));
}

// ---------------------------------------------------------------------------
// One-time fp32 -> (hi,lo) bf16 converts
// ---------------------------------------------------------------------------
__global__ __launch_bounds__(256) void convert_x_kernel(
    const float* __restrict__ q, const float* __restrict__ k, const float* __restrict__ v)
{
    int z = blockIdx.y;
    const float* src = (z == 0) ? q : (z == 1 ? k : v);
    int i = (blockIdx.x * 256 + threadIdx.x) * 4;
    float4 x = *(const float4*)(src + i);
    bf16 h0, l0, h1, l1, h2, l2, h3, l3;
    split_bf(x.x, h0, l0); split_bf(x.y, h1, l1);
    split_bf(x.z, h2, l2); split_bf(x.w, h3, l3);
    size_t base = (size_t)z * (1024*512) + i;
    bf162* ph = (bf162*)&g_Xhi[base];
    bf162* pl = (bf162*)&g_Xlo[base];
    ph[0] = bf162(h0, h1); ph[1] = bf162(h2, h3);
    pl[0] = bf162(l0, l1); pl[1] = bf162(l2, l3);
}

__global__ __launch_bounds__(256) void convert_w_kernel(
    const float* __restrict__ Wq, const float* __restrict__ Wk,
    const float* __restrict__ Wv, const float* __restrict__ W0)
{
    __shared__ float tile[32][33];
    int z = blockIdx.z;
    const float* W = (z == 0) ? Wq : (z == 1 ? Wk : (z == 2 ? Wv : W0));
    int k0 = blockIdx.x * 32, n0 = blockIdx.y * 32;
    int tx = threadIdx.x, ty = threadIdx.y;
    #pragma unroll
    for (int it = 0; it < 4; it++)
        tile[ty + it * 8][tx] = W[(size_t)(k0 + ty + it * 8) * D_ + n0 + tx];
    __syncthreads();
    size_t zb = (size_t)z * (512*512);
    #pragma unroll
    for (int it = 0; it < 4; it++) {
        int nr = ty + it * 8;
        bf16 hi, lo;
        split_bf(tile[tx][nr], hi, lo);
        g_Whi[zb + (size_t)(n0 + nr) * D_ + k0 + tx] = hi;
        g_Wlo[zb + (size_t)(n0 + nr) * D_ + k0 + tx] = lo;
    }
}

// V [bh][j][dk] fp32 -> VT [bh][dk][j] bf16 hi/lo. grid (8, 2, 32), block (32,8)
__global__ __launch_bounds__(256) void convert_vT_kernel()
{
    __shared__ float tile[32][33];
    int bh = blockIdx.z;
    int j0 = blockIdx.x * 32, d0 = blockIdx.y * 32;
    int tx = threadIdx.x, ty = threadIdx.y;
    const float* vsrc = g_vh + (size_t)bh * (L_ * DK_);
    #pragma unroll
    for (int it = 0; it < 4; it++)
        tile[ty + it * 8][tx] = vsrc[(size_t)(j0 + ty + it * 8) * DK_ + d0 + tx];
    __syncthreads();
    size_t base = (size_t)bh * (DK_ * L_);
    #pragma unroll
    for (int it = 0; it < 4; it++) {
        int nr = ty + it * 8;
        bf16 hi, lo;
        split_bf(tile[tx][nr], hi, lo);
        g_VThi[base + (size_t)(d0 + nr) * L_ + j0 + tx] = hi;
        g_VTlo[base + (size_t)(d0 + nr) * L_ + j0 + tx] = lo;
    }
}

// ---------------------------------------------------------------------------
// 3xBF16 tensor-core GEMM (R7 winner, unchanged)
// ---------------------------------------------------------------------------
#define SA 40
#define A_HALVES (128*SA)
#define B_HALVES (64*SA)
#define GEMM_BUF_H (2*A_HALVES + 2*B_HALVES)
#define GEMM_SMEM_BYTES (2*GEMM_BUF_H*2)

template<bool HEADSPLIT>
__device__ __forceinline__ void gemm_core(
    const bf16* __restrict__ Ahi_g, const bf16* __restrict__ Alo_g,
    const bf16* __restrict__ Bhi_g, const bf16* __restrict__ Blo_g,
    const float* __restrict__ bias, float* __restrict__ Y)
{
    extern __shared__ __align__(16) bf16 smh[];
    const int tid = threadIdx.x;
    const int lane = tid & 31, wid = tid >> 5;
    const int g = lane >> 2, t4 = lane & 3;
    const int warp_m = (wid & 3) * 32;
    const int warp_n = (wid >> 2) * 32;
    const int m0 = blockIdx.x * 128, n0 = blockIdx.y * 64;

    const int am = tid >> 1, ah = (tid & 1) * 16;
    const int bn = tid >> 2, bh = (tid & 3) * 8;
    const bf16* Asrc_h = Ahi_g + (size_t)(m0 + am) * D_ + ah;
    const bf16* Asrc_l = Alo_g + (size_t)(m0 + am) * D_ + ah;
    const bf16* Bsrc_h = Bhi_g + (size_t)(n0 + bn) * D_ + bh;
    const bf16* Bsrc_l = Blo_g + (size_t)(n0 + bn) * D_ + bh;

    float acc[2][4][4];
    #pragma unroll
    for (int i = 0; i < 2; i++)
        #pragma unroll
        for (int j = 0; j < 4; j++)
            #pragma unroll
            for (int c = 0; c < 4; c++) acc[i][j][c] = 0.0f;

    const int lrow = lane & 15;
    const int lk   = (lane >> 4) * 8;
    const int bln  = lane & 7;
    const int bseg = (lane >> 3) & 1;
    const int bhi16 = (lane >> 4);
    const uint32_t smem_base = smem_u32(smh);
    const uint32_t aoff0 = ((warp_m + lrow)      * SA + lk) * 2;
    const uint32_t aoff1 = ((warp_m + 16 + lrow) * SA + lk) * 2;
    const uint32_t boff0 = ((warp_n + bln)       * SA + bseg * 8) * 2 + bhi16 * (8 * SA * 2);
    const uint32_t boff1 = boff0 + 16 * SA * 2;

    uint4 rAh0, rAh1, rAl0, rAl1, rBh, rBl;
    rAh0 = *(const uint4*)(Asrc_h);  rAh1 = *(const uint4*)(Asrc_h + 8);
    rAl0 = *(const uint4*)(Asrc_l);  rAl1 = *(const uint4*)(Asrc_l + 8);
    rBh  = *(const uint4*)(Bsrc_h);  rBl  = *(const uint4*)(Bsrc_l);

    for (int s = 0; s < 16; s++) {
        const int buf = s & 1;
        bf16* Ah_s = smh + buf * GEMM_BUF_H;
        bf16* Al_s = Ah_s + A_HALVES;
        bf16* Bh_s = Al_s + A_HALVES;
        bf16* Bl_s = Bh_s + B_HALVES;

        *(uint4*)&Ah_s[am * SA + ah]     = rAh0;
        *(uint4*)&Ah_s[am * SA + ah + 8] = rAh1;
        *(uint4*)&Al_s[am * SA + ah]     = rAl0;
        *(uint4*)&Al_s[am * SA + ah + 8] = rAl1;
        *(uint4*)&Bh_s[bn * SA + bh] = rBh;
        *(uint4*)&Bl_s[bn * SA + bh] = rBl;
        __syncthreads();

        if (s < 15) {
            const int off = (s + 1) * 32;
            rAh0 = *(const uint4*)(Asrc_h + off); rAh1 = *(const uint4*)(Asrc_h + off + 8);
            rAl0 = *(const uint4*)(Asrc_l + off); rAl1 = *(const uint4*)(Asrc_l + off + 8);
            rBh  = *(const uint4*)(Bsrc_h + off); rBl  = *(const uint4*)(Bsrc_l + off);
        }

        const uint32_t base = smem_base + (uint32_t)(buf * GEMM_BUF_H * 2);
        const uint32_t aBh = base;
        const uint32_t aBl = base + A_HALVES * 2;
        const uint32_t bBh = base + 2 * A_HALVES * 2;
        const uint32_t bBl = bBh + B_HALVES * 2;

        #pragma unroll
        for (int kk = 0; kk < 2; kk++) {
            const uint32_t ko = kk * 32;
            uint32_t Ah0[4], Ah1[4], Al0[4], Al1[4];
            uint32_t Bh0[4], Bh1[4], Bl0[4], Bl1[4];
            ldm_x4(Ah0, aBh + aoff0 + ko);
            ldm_x4(Ah1, aBh + aoff1 + ko);
            ldm_x4(Al0, aBl + aoff0 + ko);
            ldm_x4(Al1, aBl + aoff1 + ko);
            ldm_x4(Bh0, bBh + boff0 + ko);
            ldm_x4(Bh1, bBh + boff1 + ko);
            ldm_x4(Bl0, bBl + boff0 + ko);
            ldm_x4(Bl1, bBl + boff1 + ko);

            #pragma unroll
            for (int i = 0; i < 2; i++) {
                uint32_t* ahp = i ? Ah1 : Ah0;
                uint32_t* alp = i ? Al1 : Al0;
                #pragma unroll
                for (int j = 0; j < 4; j++) {
                    uint32_t* bhp = (j < 2) ? Bh0 : Bh1;
                    uint32_t* blp = (j < 2) ? Bl0 : Bl1;
                    uint32_t bhf[2] = { bhp[(j & 1) * 2], bhp[(j & 1) * 2 + 1] };
                    uint32_t blf[2] = { blp[(j & 1) * 2], blp[(j & 1) * 2 + 1] };
                    mma_bf16(acc[i][j], ahp, bhf);
                    mma_bf16(acc[i][j], ahp, blf);
                    mma_bf16(acc[i][j], alp, bhf);
                }
            }
        }
    }

    #pragma unroll
    for (int i = 0; i < 2; i++) {
        #pragma unroll
        for (int j = 0; j < 4; j++) {
            int col_loc = warp_n + (j >> 1) * 16 + (j & 1) * 8 + 2 * t4;
            int cng = n0 + col_loc;
            float b0 = bias[cng], b1 = bias[cng + 1];
            int r0 = m0 + warp_m + i * 16 + g;
            int r1 = r0 + 8;
            float2 v0 = make_float2(acc[i][j][0] + b0, acc[i][j][1] + b1);
            float2 v1 = make_float2(acc[i][j][2] + b0, acc[i][j][3] + b1);
            if (HEADSPLIT) {
                int h = blockIdx.y;
                float* d0 = Y + ((size_t)((r0 >> 8) * H_ + h) * L_ + (r0 & 255)) * DK_ + col_loc;
                float* d1 = Y + ((size_t)((r1 >> 8) * H_ + h) * L_ + (r1 & 255)) * DK_ + col_loc;
                *(float2*)d0 = v0;
                *(float2*)d1 = v1;
            } else {
                *(float2*)(Y + (size_t)r0 * D_ + cng) = v0;
                *(float2*)(Y + (size_t)r1 * D_ + cng) = v1;
            }
        }
    }
}

__global__ __launch_bounds__(256, 2) void qkv_mma_kernel(
    const float* __restrict__ bq, const float* __restrict__ bk, const float* __restrict__ bv)
{
    int z = blockIdx.z;
    const float* bias = (z == 0) ? bq : (z == 1 ? bk : bv);
    float* out = (z == 0) ? g_qh : (z == 1 ? g_kh : g_vh);
    gemm_core<true>(g_Xhi + (size_t)z * (1024*512), g_Xlo + (size_t)z * (1024*512),
                    g_Whi + (size_t)z * (512*512),  g_Wlo + (size_t)z * (512*512),
                    bias, out);
}

__global__ __launch_bounds__(256, 2) void out_mma_kernel(
    const float* __restrict__ b0, float* __restrict__ Y)
{
    gemm_core<false>(g_ctx_hi, g_ctx_lo,
                     g_Whi + (size_t)3 * (512*512), g_Wlo + (size_t)3 * (512*512),
                     b0, Y);
}

// ---------------------------------------------------------------------------
// Scores kernel: E = mask ? exp(sum_d vp[d]*tanh(q+k)) : 0, written bf16 hi/lo
// grid (4, 4, 32), 256 thr, smem ~35KB.
// ---------------------------------------------------------------------------
#define SC_ST 68

__global__ __launch_bounds__(256) void scores_kernel(
    const int* __restrict__ mask, const float* __restrict__ vp)
{
    __shared__ float Qs[64 * SC_ST];
    __shared__ float Ks[64 * SC_ST];
    __shared__ float vps[64];

    const int tid = threadIdx.x;
    const int bh = blockIdx.z;
    const int b = bh >> 3, h = bh & 7;
    const int i0 = blockIdx.x * 64, j0 = blockIdx.y * 64;

    const float* qh = g_qh + (size_t)(bh * L_ + i0) * DK_;
    const float* kh = g_kh + (size_t)(bh * L_ + j0) * DK_;

    if (tid < 64) vps[tid] = vp[h * DK_ + tid];
    {
        int r = tid >> 2, d0 = (tid & 3) * 16;
        #pragma unroll
        for (int u = 0; u < 4; u++) {
            float4 tq = *(const float4*)&qh[(size_t)r * DK_ + d0 + u * 4];
            Qs[(d0 + u * 4 + 0) * SC_ST + r] = tq.x;
            Qs[(d0 + u * 4 + 1) * SC_ST + r] = tq.y;
            Qs[(d0 + u * 4 + 2) * SC_ST + r] = tq.z;
            Qs[(d0 + u * 4 + 3) * SC_ST + r] = tq.w;
            float4 tk = *(const float4*)&kh[(size_t)r * DK_ + d0 + u * 4];
            Ks[(d0 + u * 4 + 0) * SC_ST + r] = tk.x;
            Ks[(d0 + u * 4 + 1) * SC_ST + r] = tk.y;
            Ks[(d0 + u * 4 + 2) * SC_ST + r] = tk.z;
            Ks[(d0 + u * 4 + 3) * SC_ST + r] = tk.w;
        }
    }
    __syncthreads();

    const int ti = tid >> 4;   // i group (warp-broadcast Q reads)
    const int tj = tid & 15;   // j group (coalesced writes)

    float acc[4][4] = {};
    #pragma unroll 2
    for (int d = 0; d < 64; d++) {
        float w = vps[d];
        float4 qv = *(const float4*)&Qs[d * SC_ST + ti * 4];
        float4 kv = *(const float4*)&Ks[d * SC_ST + tj * 4];
        float qa[4] = {qv.x, qv.y, qv.z, qv.w};
        float kb[4] = {kv.x, kv.y, kv.z, kv.w};
        #pragma unroll
        for (int a = 0; a < 4; a++)
            #pragma unroll
            for (int c = 0; c < 4; c++)
                acc[a][c] += w * tanh_fast(qa[a] + kb[c]);
    }

    // mask + exp (bounded: |s| <= sum|vp| ~ 6) + bf16 hi/lo store
    #pragma unroll
    for (int a = 0; a < 4; a++) {
        int row = i0 + ti * 4 + a;
        const int4 m = *(const int4*)(mask + ((size_t)b * L_ + row) * L_ + j0 + tj * 4);
        float e0 = m.x ? __expf(acc[a][0]) : 0.0f;
        float e1 = m.y ? __expf(acc[a][1]) : 0.0f;
        float e2 = m.z ? __expf(acc[a][2]) : 0.0f;
        float e3 = m.w ? __expf(acc[a][3]) : 0.0f;
        bf16 h0, l0, h1, l1, h2, l2, h3, l3;
        split_bf(e0, h0, l0); split_bf(e1, h1, l1);
        split_bf(e2, h2, l2); split_bf(e3, h3, l3);
        size_t off = (size_t)bh * (L_ * L_) + (size_t)row * L_ + j0 + tj * 4;
        bf162* ph = (bf162*)&g_Ehi[off];
        bf162* pl = (bf162*)&g_Elo[off];
        ph[0] = bf162(h0, h1); ph[1] = bf162(h2, h3);
        pl[0] = bf162(l0, l1); pl[1] = bf162(l2, l3);
    }
}

// ---------------------------------------------------------------------------
// Rowsum kernel: g_rinv[bh][i] = 1 / sum_j (Ehi + Elo). grid 32, block 256.
// ---------------------------------------------------------------------------
__global__ __launch_bounds__(256) void rowsum_kernel()
{
    int bh = blockIdx.x, row = threadIdx.x;
    const bf162* ph = (const bf162*)&g_Ehi[(size_t)(bh * L_ + row) * L_];
    const bf162* pl = (const bf162*)&g_Elo[(size_t)(bh * L_ + row) * L_];
    float s = 0.0f;
    #pragma unroll 8
    for (int j2 = 0; j2 < L_ / 2; j2++) {
        float2 a = __bfloat1622float2(ph[j2]);
        float2 c = __bfloat1622float2(pl[j2]);
        s += (a.x + c.x) + (a.y + c.y);
    }
    g_rinv[bh * L_ + row] = 1.0f / s;
}

// ---------------------------------------------------------------------------
// PV via tensor cores: ctx[i][dk] = rinv[i] * sum_j E[i][j] * VT[dk][j]
// K=256 (8 stages). grid (2, 32) = 64 CTAs, 256 thr. Same smem machinery.
// ---------------------------------------------------------------------------
__global__ __launch_bounds__(256) void pv_mma_kernel()
{
    extern __shared__ __align__(16) bf16 smh[];
    const int tid = threadIdx.x;
    const int lane = tid & 31, wid = tid >> 5;
    const int g = lane >> 2, t4 = lane & 3;
    const int warp_m = (wid & 3) * 32;
    const int warp_n = (wid >> 2) * 32;
    const int m0 = blockIdx.x * 128;
    const int bhz = blockIdx.y;
    const int b = bhz >> 3, h = bhz & 7;

    const bf16* Ahi_g = g_Ehi + (size_t)bhz * (L_ * L_);
    const bf16* Alo_g = g_Elo + (size_t)bhz * (L_ * L_);
    const bf16* Bhi_g = g_VThi + (size_t)bhz * (DK_ * L_);
    const bf16* Blo_g = g_VTlo + (size_t)bhz * (DK_ * L_);

    const int am = tid >> 1, ah = (tid & 1) * 16;
    const int bn = tid >> 2, bo = (tid & 3) * 8;
    const bf16* Asrc_h = Ahi_g + (size_t)(m0 + am) * L_ + ah;
    const bf16* Asrc_l = Alo_g + (size_t)(m0 + am) * L_ + ah;
    const bf16* Bsrc_h = Bhi_g + (size_t)bn * L_ + bo;
    const bf16* Bsrc_l = Blo_g + (size_t)bn * L_ + bo;

    float acc[2][4][4];
    #pragma unroll
    for (int i = 0; i < 2; i++)
        #pragma unroll
        for (int j = 0; j < 4; j++)
            #pragma unroll
            for (int c = 0; c < 4; c++) acc[i][j][c] = 0.0f;

    const int lrow = lane & 15;
    const int lk   = (lane >> 4) * 8;
    const int bln  = lane & 7;
    const int bseg = (lane >> 3) & 1;
    const int bhi16 = (lane >> 4);
    const uint32_t smem_base = smem_u32(smh);
    const uint32_t aoff0 = ((warp_m + lrow)      * SA + lk) * 2;
    const uint32_t aoff1 = ((warp_m + 16 + lrow) * SA + lk) * 2;
    const uint32_t boff0 = ((warp_n + bln)       * SA + bseg * 8) * 2 + bhi16 * (8 * SA * 2);
    const uint32_t boff1 = boff0 + 16 * SA * 2;

    uint4 rAh0, rAh1, rAl0, rAl1, rBh, rBl;
    rAh0 = *(const uint4*)(Asrc_h);  rAh1 = *(const uint4*)(Asrc_h + 8);
    rAl0 = *(const uint4*)(Asrc_l);  rAl1 = *(const uint4*)(Asrc_l + 8);
    rBh  = *(const uint4*)(Bsrc_h);  rBl  = *(const uint4*)(Bsrc_l);

    for (int s = 0; s < 8; s++) {
        const int buf = s & 1;
        bf16* Ah_s = smh + buf * GEMM_BUF_H;
        bf16* Al_s = Ah_s + A_HALVES;
        bf16* Bh_s = Al_s + A_HALVES;
        bf16* Bl_s = Bh_s + B_HALVES;

        *(uint4*)&Ah_s[am * SA + ah]     = rAh0;
        *(uint4*)&Ah_s[am * SA + ah + 8] = rAh1;
        *(uint4*)&Al_s[am * SA + ah]     = rAl0;
        *(uint4*)&Al_s[am * SA + ah + 8] = rAl1;
        *(uint4*)&Bh_s[bn * SA + bo] = rBh;
        *(uint4*)&Bl_s[bn * SA + bo] = rBl;
        __syncthreads();

        if (s < 7) {
            const int off = (s + 1) * 32;
            rAh0 = *(const uint4*)(Asrc_h + off); rAh1 = *(const uint4*)(Asrc_h + off + 8);
            rAl0 = *(const uint4*)(Asrc_l + off); rAl1 = *(const uint4*)(Asrc_l + off + 8);
            rBh  = *(const uint4*)(Bsrc_h + off); rBl  = *(const uint4*)(Bsrc_l + off);
        }

        const uint32_t base = smem_base + (uint32_t)(buf * GEMM_BUF_H * 2);
        const uint32_t aBh = base;
        const uint32_t aBl = base + A_HALVES * 2;
        const uint32_t bBh = base + 2 * A_HALVES * 2;
        const uint32_t bBl = bBh + B_HALVES * 2;

        #pragma unroll
        for (int kk = 0; kk < 2; kk++) {
            const uint32_t ko = kk * 32;
            uint32_t Ah0[4], Ah1[4], Al0[4], Al1[4];
            uint32_t Bh0[4], Bh1[4], Bl0[4], Bl1[4];
            ldm_x4(Ah0, aBh + aoff0 + ko);
            ldm_x4(Ah1, aBh + aoff1 + ko);
            ldm_x4(Al0, aBl + aoff0 + ko);
            ldm_x4(Al1, aBl + aoff1 + ko);
            ldm_x4(Bh0, bBh + boff0 + ko);
            ldm_x4(Bh1, bBh + boff1 + ko);
            ldm_x4(Bl0, bBl + boff0 + ko);
            ldm_x4(Bl1, bBl + boff1 + ko);

            #pragma unroll
            for (int i = 0; i < 2; i++) {
                uint32_t* ahp = i ? Ah1 : Ah0;
                uint32_t* alp = i ? Al1 : Al0;
                #pragma unroll
                for (int j = 0; j < 4; j++) {
                    uint32_t* bhp = (j < 2) ? Bh0 : Bh1;
                    uint32_t* blp = (j < 2) ? Bl0 : Bl1;
                    uint32_t bhf[2] = { bhp[(j & 1) * 2], bhp[(j & 1) * 2 + 1] };
                    uint32_t blf[2] = { blp[(j & 1) * 2], blp[(j & 1) * 2 + 1] };
                    mma_bf16(acc[i][j], ahp, bhf);
                    mma_bf16(acc[i][j], ahp, blf);
                    mma_bf16(acc[i][j], alp, bhf);
                }
            }
        }
    }

    // Epilogue: scale by rinv, split to bf16 hi/lo ctx (row = b*L+i, col = h*64+dk)
    const float* rinvp = g_rinv + bhz * L_;
    #pragma unroll
    for (int i = 0; i < 2; i++) {
        #pragma unroll
        for (int j = 0; j < 4; j++) {
            int col_loc = warp_n + (j >> 1) * 16 + (j & 1) * 8 + 2 * t4;
            int r0 = m0 + warp_m + i * 16 + g;
            int r1 = r0 + 8;
            float inv0 = rinvp[r0], inv1 = rinvp[r1];
            float v00 = acc[i][j][0] * inv0, v01 = acc[i][j][1] * inv0;
            float v10 = acc[i][j][2] * inv1, v11 = acc[i][j][3] * inv1;
            bf16 ha, la, hb, lb;
            size_t o0 = ((size_t)(b * L_ + r0)) * D_ + h * DK_ + col_loc;
            size_t o1 = ((size_t)(b * L_ + r1)) * D_ + h * DK_ + col_loc;
            split_bf(v00, ha, la); split_bf(v01, hb, lb);
            *(bf162*)&g_ctx_hi[o0] = bf162(ha, hb);
            *(bf162*)&g_ctx_lo[o0] = bf162(la, lb);
            split_bf(v10, ha, la); split_bf(v11, hb, lb);
            *(bf162*)&g_ctx_hi[o1] = bf162(ha, hb);
            *(bf162*)&g_ctx_lo[o1] = bf162(la, lb);
        }
    }
}

// ===========================================================================
extern "C" void kernel_launch(void* const* d_in, const int* in_sizes, int n_in,
                              void* d_out, int out_size)
{
    const float* q    = (const float*)d_in[0];
    const float* k    = (const float*)d_in[1];
    const float* v    = (const float*)d_in[2];
    const int*   mask = (const int*)  d_in[3];
    const float* Wq   = (const float*)d_in[4];
    const float* bq   = (const float*)d_in[5];
    const float* Wk   = (const float*)d_in[6];
    const float* bk   = (const float*)d_in[7];
    const float* Wv   = (const float*)d_in[8];
    const float* bv   = (const float*)d_in[9];
    const float* vp   = (const float*)d_in[10];
    const float* W0   = (const float*)d_in[11];
    const float* b0   = (const float*)d_in[12];
    float* out = (float*)d_out;

    static bool attr_set = false;
    if (!attr_set) {
        cudaFuncSetAttribute(qkv_mma_kernel,
                             cudaFuncAttributeMaxDynamicSharedMemorySize, GEMM_SMEM_BYTES);
        cudaFuncSetAttribute(out_mma_kernel,
                             cudaFuncAttributeMaxDynamicSharedMemorySize, GEMM_SMEM_BYTES);
        cudaFuncSetAttribute(pv_mma_kernel,
                             cudaFuncAttributeMaxDynamicSharedMemorySize, GEMM_SMEM_BYTES);
        attr_set = true;
    }

    convert_x_kernel<<<dim3(512, 3), 256>>>(q, k, v);
    convert_w_kernel<<<dim3(16, 16, 4), dim3(32, 8)>>>(Wq, Wk, Wv, W0);
    qkv_mma_kernel<<<dim3(8, 8, 3), 256, GEMM_SMEM_BYTES>>>(bq, bk, bv);
    convert_vT_kernel<<<dim3(8, 2, 32), dim3(32, 8)>>>();
    scores_kernel<<<dim3(4, 4, 32), 256>>>(mask, vp);
    rowsum_kernel<<<32, 256>>>();
    pv_mma_kernel<<<dim3(2, 32), 256, GEMM_SMEM_BYTES>>>();
    out_mma_kernel<<<dim3(8, 8), 256, GEMM_SMEM_BYTES>>>(b0, out);
}

// round 13
// speedup vs baseline: 1.4675x; 1.1174x over previous
#include <cuda_runtime.h>
#include <cuda_bf16.h>
#include <cstdint>
#include <math.h>

#define B_ 4
#define L_ 256
#define D_ 512
#define H_ 8
#define DK_ 64

typedef __nv_bfloat16 bf16;
typedef __nv_bfloat162 bf162;

// ---------------------------------------------------------------------------
// Scratch (allocation-free rule: __device__ globals)
// ---------------------------------------------------------------------------
__device__ float g_qh[B_*H_*L_*DK_];
__device__ float g_kh[B_*H_*L_*DK_];
__device__ float g_vh[B_*H_*L_*DK_];
__device__ float g_rsum4[B_*H_*4*L_];               // per-jblock row partial sums

__device__ __align__(16) bf16 g_Ehi[B_*H_*L_*L_];   // exp(scores) hi
__device__ __align__(16) bf16 g_Elo[B_*H_*L_*L_];   // exp(scores) lo
__device__ __align__(16) bf16 g_VThi[B_*H_*DK_*L_]; // V^T [bh][dk][j]
__device__ __align__(16) bf16 g_VTlo[B_*H_*DK_*L_];

__device__ __align__(16) bf16 g_Xhi[3*1024*512];   // q,k,v inputs [m][k]
__device__ __align__(16) bf16 g_Xlo[3*1024*512];
__device__ __align__(16) bf16 g_Whi[4*512*512];    // Wq,Wk,Wv,W0 TRANSPOSED [n][k]
__device__ __align__(16) bf16 g_Wlo[4*512*512];
__device__ __align__(16) bf16 g_ctx_hi[1024*512];  // attention context [m][k]
__device__ __align__(16) bf16 g_ctx_lo[1024*512];

// ---------------------------------------------------------------------------
__device__ __forceinline__ uint32_t smem_u32(const void* p) {
    uint32_t a;
    asm("{ .reg .u64 t; cvta.to.shared.u64 t, %1; cvt.u32.u64 %0, t; }" : "=r"(a) : "l"(p));
    return a;
}
__device__ __forceinline__ float tanh_fast(float x) {
    float y;
    asm("tanh.approx.f32 %0, %1;" : "=f"(y) : "f"(x));
    return y;
}
__device__ __forceinline__ void ldm_x4(uint32_t* r, uint32_t addr) {
    asm volatile("ldmatrix.sync.aligned.m8n8.x4.shared.b16 {%0,%1,%2,%3}, [%4];"
        : "=r"(r[0]), "=r"(r[1]), "=r"(r[2]), "=r"(r[3]) : "r"(addr));
}
__device__ __forceinline__ void mma_bf16(float* c, const uint32_t* a, const uint32_t* b) {
    asm volatile(
        "mma.sync.aligned.m16n8k16.row.col.f32.bf16.bf16.f32 "
        "{%0,%1,%2,%3}, {%4,%5,%6,%7}, {%8,%9}, {%0,%1,%2,%3};"
        : "+f"(c[0]), "+f"(c[1]), "+f"(c[2]), "+f"(c[3])
        : "r"(a[0]), "r"(a[1]), "r"(a[2]), "r"(a[3]), "r"(b[0]), "r"(b[1]));
}
__device__ __forceinline__ void split_bf(float x, bf16& hi, bf16& lo) {
    hi = __float2bfloat16_rn(x);
    lo = __float2bfloat16_rn(x - __bfloat162float(hi));
}

// ---------------------------------------------------------------------------
// One-time fp32 -> (hi,lo) bf16 converts
// ---------------------------------------------------------------------------
__global__ __launch_bounds__(256) void convert_x_kernel(
    const float* __restrict__ q, const float* __restrict__ k, const float* __restrict__ v)
{
    int z = blockIdx.y;
    const float* src = (z == 0) ? q : (z == 1 ? k : v);
    int i = (blockIdx.x * 256 + threadIdx.x) * 4;
    float4 x = *(const float4*)(src + i);
    bf16 h0, l0, h1, l1, h2, l2, h3, l3;
    split_bf(x.x, h0, l0); split_bf(x.y, h1, l1);
    split_bf(x.z, h2, l2); split_bf(x.w, h3, l3);
    size_t base = (size_t)z * (1024*512) + i;
    bf162* ph = (bf162*)&g_Xhi[base];
    bf162* pl = (bf162*)&g_Xlo[base];
    ph[0] = bf162(h0, h1); ph[1] = bf162(h2, h3);
    pl[0] = bf162(l0, l1); pl[1] = bf162(l2, l3);
}

__global__ __launch_bounds__(256) void convert_w_kernel(
    const float* __restrict__ Wq, const float* __restrict__ Wk,
    const float* __restrict__ Wv, const float* __restrict__ W0)
{
    __shared__ float tile[32][33];
    int z = blockIdx.z;
    const float* W = (z == 0) ? Wq : (z == 1 ? Wk : (z == 2 ? Wv : W0));
    int k0 = blockIdx.x * 32, n0 = blockIdx.y * 32;
    int tx = threadIdx.x, ty = threadIdx.y;
    #pragma unroll
    for (int it = 0; it < 4; it++)
        tile[ty + it * 8][tx] = W[(size_t)(k0 + ty + it * 8) * D_ + n0 + tx];
    __syncthreads();
    size_t zb = (size_t)z * (512*512);
    #pragma unroll
    for (int it = 0; it < 4; it++) {
        int nr = ty + it * 8;
        bf16 hi, lo;
        split_bf(tile[tx][nr], hi, lo);
        g_Whi[zb + (size_t)(n0 + nr) * D_ + k0 + tx] = hi;
        g_Wlo[zb + (size_t)(n0 + nr) * D_ + k0 + tx] = lo;
    }
}

// V [bh][j][dk] fp32 -> VT [bh][dk][j] bf16 hi/lo. grid (8, 2, 32), block (32,8)
__global__ __launch_bounds__(256) void convert_vT_kernel()
{
    __shared__ float tile[32][33];
    int bh = blockIdx.z;
    int j0 = blockIdx.x * 32, d0 = blockIdx.y * 32;
    int tx = threadIdx.x, ty = threadIdx.y;
    const float* vsrc = g_vh + (size_t)bh * (L_ * DK_);
    #pragma unroll
    for (int it = 0; it < 4; it++)
        tile[ty + it * 8][tx] = vsrc[(size_t)(j0 + ty + it * 8) * DK_ + d0 + tx];
    __syncthreads();
    size_t base = (size_t)bh * (DK_ * L_);
    #pragma unroll
    for (int it = 0; it < 4; it++) {
        int nr = ty + it * 8;
        bf16 hi, lo;
        split_bf(tile[tx][nr], hi, lo);
        g_VThi[base + (size_t)(d0 + nr) * L_ + j0 + tx] = hi;
        g_VTlo[base + (size_t)(d0 + nr) * L_ + j0 + tx] = lo;
    }
}

// ---------------------------------------------------------------------------
// 3xBF16 tensor-core GEMM (R7 winner, unchanged)
// ---------------------------------------------------------------------------
#define SA 40
#define A_HALVES (128*SA)
#define B_HALVES (64*SA)
#define GEMM_BUF_H (2*A_HALVES + 2*B_HALVES)
#define GEMM_SMEM_BYTES (2*GEMM_BUF_H*2)

template<bool HEADSPLIT>
__device__ __forceinline__ void gemm_core(
    const bf16* __restrict__ Ahi_g, const bf16* __restrict__ Alo_g,
    const bf16* __restrict__ Bhi_g, const bf16* __restrict__ Blo_g,
    const float* __restrict__ bias, float* __restrict__ Y)
{
    extern __shared__ __align__(16) bf16 smh[];
    const int tid = threadIdx.x;
    const int lane = tid & 31, wid = tid >> 5;
    const int g = lane >> 2, t4 = lane & 3;
    const int warp_m = (wid & 3) * 32;
    const int warp_n = (wid >> 2) * 32;
    const int m0 = blockIdx.x * 128, n0 = blockIdx.y * 64;

    const int am = tid >> 1, ah = (tid & 1) * 16;
    const int bn = tid >> 2, bh = (tid & 3) * 8;
    const bf16* Asrc_h = Ahi_g + (size_t)(m0 + am) * D_ + ah;
    const bf16* Asrc_l = Alo_g + (size_t)(m0 + am) * D_ + ah;
    const bf16* Bsrc_h = Bhi_g + (size_t)(n0 + bn) * D_ + bh;
    const bf16* Bsrc_l = Blo_g + (size_t)(n0 + bn) * D_ + bh;

    float acc[2][4][4];
    #pragma unroll
    for (int i = 0; i < 2; i++)
        #pragma unroll
        for (int j = 0; j < 4; j++)
            #pragma unroll
            for (int c = 0; c < 4; c++) acc[i][j][c] = 0.0f;

    const int lrow = lane & 15;
    const int lk   = (lane >> 4) * 8;
    const int bln  = lane & 7;
    const int bseg = (lane >> 3) & 1;
    const int bhi16 = (lane >> 4);
    const uint32_t smem_base = smem_u32(smh);
    const uint32_t aoff0 = ((warp_m + lrow)      * SA + lk) * 2;
    const uint32_t aoff1 = ((warp_m + 16 + lrow) * SA + lk) * 2;
    const uint32_t boff0 = ((warp_n + bln)       * SA + bseg * 8) * 2 + bhi16 * (8 * SA * 2);
    const uint32_t boff1 = boff0 + 16 * SA * 2;

    uint4 rAh0, rAh1, rAl0, rAl1, rBh, rBl;
    rAh0 = *(const uint4*)(Asrc_h);  rAh1 = *(const uint4*)(Asrc_h + 8);
    rAl0 = *(const uint4*)(Asrc_l);  rAl1 = *(const uint4*)(Asrc_l + 8);
    rBh  = *(const uint4*)(Bsrc_h);  rBl  = *(const uint4*)(Bsrc_l);

    for (int s = 0; s < 16; s++) {
        const int buf = s & 1;
        bf16* Ah_s = smh + buf * GEMM_BUF_H;
        bf16* Al_s = Ah_s + A_HALVES;
        bf16* Bh_s = Al_s + A_HALVES;
        bf16* Bl_s = Bh_s + B_HALVES;

        *(uint4*)&Ah_s[am * SA + ah]     = rAh0;
        *(uint4*)&Ah_s[am * SA + ah + 8] = rAh1;
        *(uint4*)&Al_s[am * SA + ah]     = rAl0;
        *(uint4*)&Al_s[am * SA + ah + 8] = rAl1;
        *(uint4*)&Bh_s[bn * SA + bh] = rBh;
        *(uint4*)&Bl_s[bn * SA + bh] = rBl;
        __syncthreads();

        if (s < 15) {
            const int off = (s + 1) * 32;
            rAh0 = *(const uint4*)(Asrc_h + off); rAh1 = *(const uint4*)(Asrc_h + off + 8);
            rAl0 = *(const uint4*)(Asrc_l + off); rAl1 = *(const uint4*)(Asrc_l + off + 8);
            rBh  = *(const uint4*)(Bsrc_h + off); rBl  = *(const uint4*)(Bsrc_l + off);
        }

        const uint32_t base = smem_base + (uint32_t)(buf * GEMM_BUF_H * 2);
        const uint32_t aBh = base;
        const uint32_t aBl = base + A_HALVES * 2;
        const uint32_t bBh = base + 2 * A_HALVES * 2;
        const uint32_t bBl = bBh + B_HALVES * 2;

        #pragma unroll
        for (int kk = 0; kk < 2; kk++) {
            const uint32_t ko = kk * 32;
            uint32_t Ah0[4], Ah1[4], Al0[4], Al1[4];
            uint32_t Bh0[4], Bh1[4], Bl0[4], Bl1[4];
            ldm_x4(Ah0, aBh + aoff0 + ko);
            ldm_x4(Ah1, aBh + aoff1 + ko);
            ldm_x4(Al0, aBl + aoff0 + ko);
            ldm_x4(Al1, aBl + aoff1 + ko);
            ldm_x4(Bh0, bBh + boff0 + ko);
            ldm_x4(Bh1, bBh + boff1 + ko);
            ldm_x4(Bl0, bBl + boff0 + ko);
            ldm_x4(Bl1, bBl + boff1 + ko);

            #pragma unroll
            for (int i = 0; i < 2; i++) {
                uint32_t* ahp = i ? Ah1 : Ah0;
                uint32_t* alp = i ? Al1 : Al0;
                #pragma unroll
                for (int j = 0; j < 4; j++) {
                    uint32_t* bhp = (j < 2) ? Bh0 : Bh1;
                    uint32_t* blp = (j < 2) ? Bl0 : Bl1;
                    uint32_t bhf[2] = { bhp[(j & 1) * 2], bhp[(j & 1) * 2 + 1] };
                    uint32_t blf[2] = { blp[(j & 1) * 2], blp[(j & 1) * 2 + 1] };
                    mma_bf16(acc[i][j], ahp, bhf);
                    mma_bf16(acc[i][j], ahp, blf);
                    mma_bf16(acc[i][j], alp, bhf);
                }
            }
        }
    }

    #pragma unroll
    for (int i = 0; i < 2; i++) {
        #pragma unroll
        for (int j = 0; j < 4; j++) {
            int col_loc = warp_n + (j >> 1) * 16 + (j & 1) * 8 + 2 * t4;
            int cng = n0 + col_loc;
            float b0 = bias[cng], b1 = bias[cng + 1];
            int r0 = m0 + warp_m + i * 16 + g;
            int r1 = r0 + 8;
            float2 v0 = make_float2(acc[i][j][0] + b0, acc[i][j][1] + b1);
            float2 v1 = make_float2(acc[i][j][2] + b0, acc[i][j][3] + b1);
            if (HEADSPLIT) {
                int h = blockIdx.y;
                float* d0 = Y + ((size_t)((r0 >> 8) * H_ + h) * L_ + (r0 & 255)) * DK_ + col_loc;
                float* d1 = Y + ((size_t)((r1 >> 8) * H_ + h) * L_ + (r1 & 255)) * DK_ + col_loc;
                *(float2*)d0 = v0;
                *(float2*)d1 = v1;
            } else {
                *(float2*)(Y + (size_t)r0 * D_ + cng) = v0;
                *(float2*)(Y + (size_t)r1 * D_ + cng) = v1;
            }
        }
    }
}

__global__ __launch_bounds__(256, 2) void qkv_mma_kernel(
    const float* __restrict__ bq, const float* __restrict__ bk, const float* __restrict__ bv)
{
    int z = blockIdx.z;
    const float* bias = (z == 0) ? bq : (z == 1 ? bk : bv);
    float* out = (z == 0) ? g_qh : (z == 1 ? g_kh : g_vh);
    gemm_core<true>(g_Xhi + (size_t)z * (1024*512), g_Xlo + (size_t)z * (1024*512),
                    g_Whi + (size_t)z * (512*512),  g_Wlo + (size_t)z * (512*512),
                    bias, out);
}

__global__ __launch_bounds__(256, 2) void out_mma_kernel(
    const float* __restrict__ b0, float* __restrict__ Y)
{
    gemm_core<false>(g_ctx_hi, g_ctx_lo,
                     g_Whi + (size_t)3 * (512*512), g_Wlo + (size_t)3 * (512*512),
                     b0, Y);
}

// ---------------------------------------------------------------------------
// Scores v2: grid (8, 4, 32) = 1024 CTAs, 256 thr, smem ~26KB (8 CTAs/SM).
// i-tile 32, j-tile 64; thread = 2i x 4j (8 tanh per LDS pair).
// Writes E bf16 hi/lo + per-jblock row partial sums (shfl-reduced).
// ---------------------------------------------------------------------------
#define SCQ_ST 34
#define SCK_ST 68

__global__ __launch_bounds__(256) void scores_kernel(
    const int* __restrict__ mask, const float* __restrict__ vp)
{
    __shared__ float Qs[32 * SCQ_ST < 64 * SCQ_ST ? 64 * SCQ_ST : 64 * SCQ_ST]; // 64 x 34 (d-major)
    __shared__ float Ks[64 * SCK_ST];
    __shared__ float vps[64];

    const int tid = threadIdx.x;
    const int bh = blockIdx.z;
    const int b = bh >> 3, h = bh & 7;
    const int i0 = blockIdx.x * 32, j0 = blockIdx.y * 64;
    const int jb = blockIdx.y;

    const float* qh = g_qh + (size_t)(bh * L_ + i0) * DK_;
    const float* kh = g_kh + (size_t)(bh * L_ + j0) * DK_;

    if (tid < 64) vps[tid] = vp[h * DK_ + tid];
    // Q: 32 rows x 64 d -> Qs[d][i], thread loads 8 d's of one row
    {
        int r = tid >> 3, d0 = (tid & 7) * 8;
        float4 t0 = *(const float4*)&qh[(size_t)r * DK_ + d0];
        float4 t1 = *(const float4*)&qh[(size_t)r * DK_ + d0 + 4];
        Qs[(d0 + 0) * SCQ_ST + r] = t0.x; Qs[(d0 + 1) * SCQ_ST + r] = t0.y;
        Qs[(d0 + 2) * SCQ_ST + r] = t0.z; Qs[(d0 + 3) * SCQ_ST + r] = t0.w;
        Qs[(d0 + 4) * SCQ_ST + r] = t1.x; Qs[(d0 + 5) * SCQ_ST + r] = t1.y;
        Qs[(d0 + 6) * SCQ_ST + r] = t1.z; Qs[(d0 + 7) * SCQ_ST + r] = t1.w;
    }
    // K: 64 rows x 64 d -> Ks[d][j]
    {
        int r = tid >> 2, d0 = (tid & 3) * 16;
        #pragma unroll
        for (int u = 0; u < 4; u++) {
            float4 t = *(const float4*)&kh[(size_t)r * DK_ + d0 + u * 4];
            Ks[(d0 + u * 4 + 0) * SCK_ST + r] = t.x;
            Ks[(d0 + u * 4 + 1) * SCK_ST + r] = t.y;
            Ks[(d0 + u * 4 + 2) * SCK_ST + r] = t.z;
            Ks[(d0 + u * 4 + 3) * SCK_ST + r] = t.w;
        }
    }
    __syncthreads();

    const int il2 = tid >> 4;   // 16 groups x 2 rows
    const int jg  = tid & 15;   // 16 groups x 4 cols (coalesced stores)

    float acc[2][4] = {};
    #pragma unroll 2
    for (int d = 0; d < 64; d++) {
        float w = vps[d];
        float2 qv = *(const float2*)&Qs[d * SCQ_ST + il2 * 2];
        float4 kv = *(const float4*)&Ks[d * SCK_ST + jg * 4];
        float qa[2] = {qv.x, qv.y};
        float kb[4] = {kv.x, kv.y, kv.z, kv.w};
        #pragma unroll
        for (int a = 0; a < 2; a++)
            #pragma unroll
            for (int c = 0; c < 4; c++)
                acc[a][c] += w * tanh_fast(qa[a] + kb[c]);
    }

    // mask + exp + bf16 hi/lo store + row partial sums
    float rpart[2];
    #pragma unroll
    for (int a = 0; a < 2; a++) {
        int row = i0 + il2 * 2 + a;
        const int4 m = *(const int4*)(mask + ((size_t)b * L_ + row) * L_ + j0 + jg * 4);
        float e0 = m.x ? __expf(acc[a][0]) : 0.0f;
        float e1 = m.y ? __expf(acc[a][1]) : 0.0f;
        float e2 = m.z ? __expf(acc[a][2]) : 0.0f;
        float e3 = m.w ? __expf(acc[a][3]) : 0.0f;
        rpart[a] = (e0 + e1) + (e2 + e3);
        bf16 h0, l0, h1, l1, h2, l2, h3, l3;
        split_bf(e0, h0, l0); split_bf(e1, h1, l1);
        split_bf(e2, h2, l2); split_bf(e3, h3, l3);
        size_t off = (size_t)bh * (L_ * L_) + (size_t)row * L_ + j0 + jg * 4;
        bf162* ph = (bf162*)&g_Ehi[off];
        bf162* pl = (bf162*)&g_Elo[off];
        ph[0] = bf162(h0, h1); ph[1] = bf162(h2, h3);
        pl[0] = bf162(l0, l1); pl[1] = bf162(l2, l3);
    }
    // reduce partials across the 16 jg lanes (xor masks stay within 16-lane half)
    #pragma unroll
    for (int a = 0; a < 2; a++) {
        #pragma unroll
        for (int off = 8; off > 0; off >>= 1)
            rpart[a] += __shfl_xor_sync(0xFFFFFFFFu, rpart[a], off);
    }
    if (jg == 0) {
        int row = i0 + il2 * 2;
        float* dst = g_rsum4 + ((size_t)(bh * 4 + jb)) * L_ + row;
        dst[0] = rpart[0];
        dst[1] = rpart[1];
    }
}

// ---------------------------------------------------------------------------
// PV via tensor cores: ctx[i][dk] = (1/rowsum) * sum_j E[i][j] * VT[dk][j]
// K=256 (8 stages). grid (2, 32) = 64 CTAs, 256 thr.
// ---------------------------------------------------------------------------
__global__ __launch_bounds__(256) void pv_mma_kernel()
{
    extern __shared__ __align__(16) bf16 smh[];
    const int tid = threadIdx.x;
    const int lane = tid & 31, wid = tid >> 5;
    const int g = lane >> 2, t4 = lane & 3;
    const int warp_m = (wid & 3) * 32;
    const int warp_n = (wid >> 2) * 32;
    const int m0 = blockIdx.x * 128;
    const int bhz = blockIdx.y;
    const int b = bhz >> 3, h = bhz & 7;

    const bf16* Ahi_g = g_Ehi + (size_t)bhz * (L_ * L_);
    const bf16* Alo_g = g_Elo + (size_t)bhz * (L_ * L_);
    const bf16* Bhi_g = g_VThi + (size_t)bhz * (DK_ * L_);
    const bf16* Blo_g = g_VTlo + (size_t)bhz * (DK_ * L_);

    const int am = tid >> 1, ah = (tid & 1) * 16;
    const int bn = tid >> 2, bo = (tid & 3) * 8;
    const bf16* Asrc_h = Ahi_g + (size_t)(m0 + am) * L_ + ah;
    const bf16* Asrc_l = Alo_g + (size_t)(m0 + am) * L_ + ah;
    const bf16* Bsrc_h = Bhi_g + (size_t)bn * L_ + bo;
    const bf16* Bsrc_l = Blo_g + (size_t)bn * L_ + bo;

    float acc[2][4][4];
    #pragma unroll
    for (int i = 0; i < 2; i++)
        #pragma unroll
        for (int j = 0; j < 4; j++)
            #pragma unroll
            for (int c = 0; c < 4; c++) acc[i][j][c] = 0.0f;

    const int lrow = lane & 15;
    const int lk   = (lane >> 4) * 8;
    const int bln  = lane & 7;
    const int bseg = (lane >> 3) & 1;
    const int bhi16 = (lane >> 4);
    const uint32_t smem_base = smem_u32(smh);
    const uint32_t aoff0 = ((warp_m + lrow)      * SA + lk) * 2;
    const uint32_t aoff1 = ((warp_m + 16 + lrow) * SA + lk) * 2;
    const uint32_t boff0 = ((warp_n + bln)       * SA + bseg * 8) * 2 + bhi16 * (8 * SA * 2);
    const uint32_t boff1 = boff0 + 16 * SA * 2;

    uint4 rAh0, rAh1, rAl0, rAl1, rBh, rBl;
    rAh0 = *(const uint4*)(Asrc_h);  rAh1 = *(const uint4*)(Asrc_h + 8);
    rAl0 = *(const uint4*)(Asrc_l);  rAl1 = *(const uint4*)(Asrc_l + 8);
    rBh  = *(const uint4*)(Bsrc_h);  rBl  = *(const uint4*)(Bsrc_l);

    for (int s = 0; s < 8; s++) {
        const int buf = s & 1;
        bf16* Ah_s = smh + buf * GEMM_BUF_H;
        bf16* Al_s = Ah_s + A_HALVES;
        bf16* Bh_s = Al_s + A_HALVES;
        bf16* Bl_s = Bh_s + B_HALVES;

        *(uint4*)&Ah_s[am * SA + ah]     = rAh0;
        *(uint4*)&Ah_s[am * SA + ah + 8] = rAh1;
        *(uint4*)&Al_s[am * SA + ah]     = rAl0;
        *(uint4*)&Al_s[am * SA + ah + 8] = rAl1;
        *(uint4*)&Bh_s[bn * SA + bo] = rBh;
        *(uint4*)&Bl_s[bn * SA + bo] = rBl;
        __syncthreads();

        if (s < 7) {
            const int off = (s + 1) * 32;
            rAh0 = *(const uint4*)(Asrc_h + off); rAh1 = *(const uint4*)(Asrc_h + off + 8);
            rAl0 = *(const uint4*)(Asrc_l + off); rAl1 = *(const uint4*)(Asrc_l + off + 8);
            rBh  = *(const uint4*)(Bsrc_h + off); rBl  = *(const uint4*)(Bsrc_l + off);
        }

        const uint32_t base = smem_base + (uint32_t)(buf * GEMM_BUF_H * 2);
        const uint32_t aBh = base;
        const uint32_t aBl = base + A_HALVES * 2;
        const uint32_t bBh = base + 2 * A_HALVES * 2;
        const uint32_t bBl = bBh + B_HALVES * 2;

        #pragma unroll
        for (int kk = 0; kk < 2; kk++) {
            const uint32_t ko = kk * 32;
            uint32_t Ah0[4], Ah1[4], Al0[4], Al1[4];
            uint32_t Bh0[4], Bh1[4], Bl0[4], Bl1[4];
            ldm_x4(Ah0, aBh + aoff0 + ko);
            ldm_x4(Ah1, aBh + aoff1 + ko);
            ldm_x4(Al0, aBl + aoff0 + ko);
            ldm_x4(Al1, aBl + aoff1 + ko);
            ldm_x4(Bh0, bBh + boff0 + ko);
            ldm_x4(Bh1, bBh + boff1 + ko);
            ldm_x4(Bl0, bBl + boff0 + ko);
            ldm_x4(Bl1, bBl + boff1 + ko);

            #pragma unroll
            for (int i = 0; i < 2; i++) {
                uint32_t* ahp = i ? Ah1 : Ah0;
                uint32_t* alp = i ? Al1 : Al0;
                #pragma unroll
                for (int j = 0; j < 4; j++) {
                    uint32_t* bhp = (j < 2) ? Bh0 : Bh1;
                    uint32_t* blp = (j < 2) ? Bl0 : Bl1;
                    uint32_t bhf[2] = { bhp[(j & 1) * 2], bhp[(j & 1) * 2 + 1] };
                    uint32_t blf[2] = { blp[(j & 1) * 2], blp[(j & 1) * 2 + 1] };
                    mma_bf16(acc[i][j], ahp, bhf);
                    mma_bf16(acc[i][j], ahp, blf);
                    mma_bf16(acc[i][j], alp, bhf);
                }
            }
        }
    }

    // Epilogue: inv = 1/sum(4 jb partials); scale; bf16 hi/lo ctx store
    const float* rs = g_rsum4 + (size_t)(bhz * 4) * L_;
    #pragma unroll
    for (int i = 0; i < 2; i++) {
        #pragma unroll
        for (int j = 0; j < 4; j++) {
            int col_loc = warp_n + (j >> 1) * 16 + (j & 1) * 8 + 2 * t4;
            int r0 = m0 + warp_m + i * 16 + g;
            int r1 = r0 + 8;
            float inv0 = 1.0f / (((rs[r0] + rs[L_ + r0]) + (rs[2 * L_ + r0] + rs[3 * L_ + r0])));
            float inv1 = 1.0f / (((rs[r1] + rs[L_ + r1]) + (rs[2 * L_ + r1] + rs[3 * L_ + r1])));
            float v00 = acc[i][j][0] * inv0, v01 = acc[i][j][1] * inv0;
            float v10 = acc[i][j][2] * inv1, v11 = acc[i][j][3] * inv1;
            bf16 ha, la, hb, lb;
            size_t o0 = ((size_t)(b * L_ + r0)) * D_ + h * DK_ + col_loc;
            size_t o1 = ((size_t)(b * L_ + r1)) * D_ + h * DK_ + col_loc;
            split_bf(v00, ha, la); split_bf(v01, hb, lb);
            *(bf162*)&g_ctx_hi[o0] = bf162(ha, hb);
            *(bf162*)&g_ctx_lo[o0] = bf162(la, lb);
            split_bf(v10, ha, la); split_bf(v11, hb, lb);
            *(bf162*)&g_ctx_hi[o1] = bf162(ha, hb);
            *(bf162*)&g_ctx_lo[o1] = bf162(la, lb);
        }
    }
}

// ===========================================================================
extern "C" void kernel_launch(void* const* d_in, const int* in_sizes, int n_in,
                              void* d_out, int out_size)
{
    const float* q    = (const float*)d_in[0];
    const float* k    = (const float*)d_in[1];
    const float* v    = (const float*)d_in[2];
    const int*   mask = (const int*)  d_in[3];
    const float* Wq   = (const float*)d_in[4];
    const float* bq   = (const float*)d_in[5];
    const float* Wk   = (const float*)d_in[6];
    const float* bk   = (const float*)d_in[7];
    const float* Wv   = (const float*)d_in[8];
    const float* bv   = (const float*)d_in[9];
    const float* vp   = (const float*)d_in[10];
    const float* W0   = (const float*)d_in[11];
    const float* b0   = (const float*)d_in[12];
    float* out = (float*)d_out;

    static bool attr_set = false;
    if (!attr_set) {
        cudaFuncSetAttribute(qkv_mma_kernel,
                             cudaFuncAttributeMaxDynamicSharedMemorySize, GEMM_SMEM_BYTES);
        cudaFuncSetAttribute(out_mma_kernel,
                             cudaFuncAttributeMaxDynamicSharedMemorySize, GEMM_SMEM_BYTES);
        cudaFuncSetAttribute(pv_mma_kernel,
                             cudaFuncAttributeMaxDynamicSharedMemorySize, GEMM_SMEM_BYTES);
        attr_set = true;
    }

    convert_x_kernel<<<dim3(512, 3), 256>>>(q, k, v);
    convert_w_kernel<<<dim3(16, 16, 4), dim3(32, 8)>>>(Wq, Wk, Wv, W0);
    qkv_mma_kernel<<<dim3(8, 8, 3), 256, GEMM_SMEM_BYTES>>>(bq, bk, bv);
    convert_vT_kernel<<<dim3(8, 2, 32), dim3(32, 8)>>>();
    scores_kernel<<<dim3(8, 4, 32), 256>>>(mask, vp);
    pv_mma_kernel<<<dim3(2, 32), 256, GEMM_SMEM_BYTES>>>();
    out_mma_kernel<<<dim3(8, 8), 256, GEMM_SMEM_BYTES>>>(b0, out);
}

// round 14
// speedup vs baseline: 1.5588x; 1.0622x over previous
#include <cuda_runtime.h>
#include <cuda_bf16.h>
#include <cstdint>
#include <math.h>

#define B_ 4
#define L_ 256
#define D_ 512
#define H_ 8
#define DK_ 64

typedef __nv_bfloat16 bf16;
typedef __nv_bfloat162 bf162;

// ---------------------------------------------------------------------------
// Scratch (allocation-free rule: __device__ globals)
// ---------------------------------------------------------------------------
__device__ float g_qh[B_*H_*L_*DK_];
__device__ float g_kh[B_*H_*L_*DK_];
__device__ float g_vh[B_*H_*L_*DK_];
__device__ float g_rsum4[B_*H_*4*L_];               // per-jblock row partial sums

__device__ __align__(16) bf16 g_Ehi[B_*H_*L_*L_];   // exp(scores) hi
__device__ __align__(16) bf16 g_Elo[B_*H_*L_*L_];   // exp(scores) lo
__device__ __align__(16) bf16 g_VThi[B_*H_*DK_*L_]; // V^T [bh][dk][j]
__device__ __align__(16) bf16 g_VTlo[B_*H_*DK_*L_];

__device__ __align__(16) bf16 g_Whi[4*512*512];    // Wq,Wk,Wv,W0 TRANSPOSED [n][k]
__device__ __align__(16) bf16 g_Wlo[4*512*512];
__device__ __align__(16) bf16 g_ctx_hi[1024*512];  // attention context [m][k]
__device__ __align__(16) bf16 g_ctx_lo[1024*512];

// ---------------------------------------------------------------------------
__device__ __forceinline__ uint32_t smem_u32(const void* p) {
    uint32_t a;
    asm("{ .reg .u64 t; cvta.to.shared.u64 t, %1; cvt.u32.u64 %0, t; }" : "=r"(a) : "l"(p));
    return a;
}
__device__ __forceinline__ float tanh_fast(float x) {
    float y;
    asm("tanh.approx.f32 %0, %1;" : "=f"(y) : "f"(x));
    return y;
}
__device__ __forceinline__ void ldm_x4(uint32_t* r, uint32_t addr) {
    asm volatile("ldmatrix.sync.aligned.m8n8.x4.shared.b16 {%0,%1,%2,%3}, [%4];"
        : "=r"(r[0]), "=r"(r[1]), "=r"(r[2]), "=r"(r[3]) : "r"(addr));
}
__device__ __forceinline__ void mma_bf16(float* c, const uint32_t* a, const uint32_t* b) {
    asm volatile(
        "mma.sync.aligned.m16n8k16.row.col.f32.bf16.bf16.f32 "
        "{%0,%1,%2,%3}, {%4,%5,%6,%7}, {%8,%9}, {%0,%1,%2,%3};"
        : "+f"(c[0]), "+f"(c[1]), "+f"(c[2]), "+f"(c[3])
        : "r"(a[0]), "r"(a[1]), "r"(a[2]), "r"(a[3]), "r"(b[0]), "r"(b[1]));
}
__device__ __forceinline__ void split_bf(float x, bf16& hi, bf16& lo) {
    hi = __float2bfloat16_rn(x);
    lo = __float2bfloat16_rn(x - __bfloat162float(hi));
}
__device__ __forceinline__ void split2u(float a, float b, uint32_t& h, uint32_t& l) {
    bf16 ha, la, hb, lb;
    split_bf(a, ha, la);
    split_bf(b, hb, lb);
    bf162 hh(ha, hb), ll(la, lb);
    h = *(uint32_t*)&hh;
    l = *(uint32_t*)&ll;
}

// ---------------------------------------------------------------------------
// W [k][n] -> [n][k] transpose + hi/lo split.  block (32,8), grid (16,16,4)
// ---------------------------------------------------------------------------
__global__ __launch_bounds__(256) void convert_w_kernel(
    const float* __restrict__ Wq, const float* __restrict__ Wk,
    const float* __restrict__ Wv, const float* __restrict__ W0)
{
    __shared__ float tile[32][33];
    int z = blockIdx.z;
    const float* W = (z == 0) ? Wq : (z == 1 ? Wk : (z == 2 ? Wv : W0));
    int k0 = blockIdx.x * 32, n0 = blockIdx.y * 32;
    int tx = threadIdx.x, ty = threadIdx.y;
    #pragma unroll
    for (int it = 0; it < 4; it++)
        tile[ty + it * 8][tx] = W[(size_t)(k0 + ty + it * 8) * D_ + n0 + tx];
    __syncthreads();
    size_t zb = (size_t)z * (512*512);
    #pragma unroll
    for (int it = 0; it < 4; it++) {
        int nr = ty + it * 8;
        bf16 hi, lo;
        split_bf(tile[tx][nr], hi, lo);
        g_Whi[zb + (size_t)(n0 + nr) * D_ + k0 + tx] = hi;
        g_Wlo[zb + (size_t)(n0 + nr) * D_ + k0 + tx] = lo;
    }
}

// V [bh][j][dk] fp32 -> VT [bh][dk][j] bf16 hi/lo. grid (8, 2, 32), block (32,8)
__global__ __launch_bounds__(256) void convert_vT_kernel()
{
    __shared__ float tile[32][33];
    int bh = blockIdx.z;
    int j0 = blockIdx.x * 32, d0 = blockIdx.y * 32;
    int tx = threadIdx.x, ty = threadIdx.y;
    const float* vsrc = g_vh + (size_t)bh * (L_ * DK_);
    #pragma unroll
    for (int it = 0; it < 4; it++)
        tile[ty + it * 8][tx] = vsrc[(size_t)(j0 + ty + it * 8) * DK_ + d0 + tx];
    __syncthreads();
    size_t base = (size_t)bh * (DK_ * L_);
    #pragma unroll
    for (int it = 0; it < 4; it++) {
        int nr = ty + it * 8;
        bf16 hi, lo;
        split_bf(tile[tx][nr], hi, lo);
        g_VThi[base + (size_t)(d0 + nr) * L_ + j0 + tx] = hi;
        g_VTlo[base + (size_t)(d0 + nr) * L_ + j0 + tx] = lo;
    }
}

// ---------------------------------------------------------------------------
// 3xBF16 tensor-core GEMM, templated tile width.
//   NT      : N tile (64 or 128)
//   HEADSPLIT : head-split output layout
//   AFP32   : A read as fp32 and split in registers (fuses convert_x)
// M tile fixed 128, K = 512, 16 K-stages of 32, double-buffered, ldmatrix.
// ---------------------------------------------------------------------------
#define SA 40
#define A_HALVES (128*SA)

constexpr int gemm_smem_b(int nt) {
    return 2 * (2 * A_HALVES + 2 * nt * SA) * 2;
}

template<int NT, bool HEADSPLIT, bool AFP32>
__device__ __forceinline__ void gemm_core(
    const float* __restrict__ Af_g,
    const bf16* __restrict__ Ahi_g, const bf16* __restrict__ Alo_g,
    const bf16* __restrict__ Bhi_g, const bf16* __restrict__ Blo_g,
    const float* __restrict__ bias, float* __restrict__ Y)
{
    constexpr int NTILES = NT / 16;        // j tiles per warp (8-wide)
    constexpr int NB = NTILES / 2;         // 16-wide n blocks per warp
    constexpr int B_HALVES_T = NT * SA;
    constexpr int BUF_H = 2 * A_HALVES + 2 * B_HALVES_T;
    constexpr int TPRB = 256 / NT;         // threads per B row (4 or 2)
    constexpr int BPT = NT / 64;           // uint4 per thread per side (1 or 2)

    extern __shared__ __align__(16) bf16 smh[];
    const int tid = threadIdx.x;
    const int lane = tid & 31, wid = tid >> 5;
    const int g = lane >> 2, t4 = lane & 3;
    const int warp_m = (wid & 3) * 32;
    const int warp_n = (wid >> 2) * (NT / 2);
    const int m0 = blockIdx.x * 128, n0 = blockIdx.y * NT;

    const int am = tid >> 1, ahh = (tid & 1) * 16;
    const int bn = tid / TPRB, bo = (tid % TPRB) * (32 / TPRB);

    const float* Af = Af_g ? Af_g + (size_t)(m0 + am) * D_ + ahh : (const float*)0;
    const bf16* Ash = Ahi_g ? Ahi_g + (size_t)(m0 + am) * D_ + ahh : (const bf16*)0;
    const bf16* Asl = Alo_g ? Alo_g + (size_t)(m0 + am) * D_ + ahh : (const bf16*)0;
    const bf16* Bsh = Bhi_g + (size_t)(n0 + bn) * D_ + bo;
    const bf16* Bsl = Blo_g + (size_t)(n0 + bn) * D_ + bo;

    float acc[2][NTILES][4];
    #pragma unroll
    for (int i = 0; i < 2; i++)
        #pragma unroll
        for (int j = 0; j < NTILES; j++)
            #pragma unroll
            for (int c = 0; c < 4; c++) acc[i][j][c] = 0.0f;

    const int lrow = lane & 15;
    const int lk   = (lane >> 4) * 8;
    const int bln  = lane & 7;
    const int bseg = (lane >> 3) & 1;
    const int bhi16 = (lane >> 4);
    const uint32_t smem_base = smem_u32(smh);
    const uint32_t aoff0 = ((warp_m + lrow)      * SA + lk) * 2;
    const uint32_t aoff1 = ((warp_m + 16 + lrow) * SA + lk) * 2;
    uint32_t boffs[NB];
    #pragma unroll
    for (int t = 0; t < NB; t++)
        boffs[t] = ((warp_n + t * 16 + bln) * SA + bseg * 8) * 2 + bhi16 * (8 * SA * 2);

    float4 rAf[4];
    uint4 rA_h[2], rA_l[2];
    uint4 rB_h[BPT], rB_l[BPT];

    if (AFP32) {
        #pragma unroll
        for (int u = 0; u < 4; u++) rAf[u] = *(const float4*)(Af + u * 4);
    } else {
        rA_h[0] = *(const uint4*)(Ash);     rA_h[1] = *(const uint4*)(Ash + 8);
        rA_l[0] = *(const uint4*)(Asl);     rA_l[1] = *(const uint4*)(Asl + 8);
    }
    #pragma unroll
    for (int p = 0; p < BPT; p++) {
        rB_h[p] = *(const uint4*)(Bsh + p * 8);
        rB_l[p] = *(const uint4*)(Bsl + p * 8);
    }

    for (int s = 0; s < 16; s++) {
        const int buf = s & 1;
        bf16* Ah_s = smh + buf * BUF_H;
        bf16* Al_s = Ah_s + A_HALVES;
        bf16* Bh_s = Al_s + A_HALVES;
        bf16* Bl_s = Bh_s + B_HALVES_T;

        if (AFP32) {
            uint32_t h[8], l[8];
            #pragma unroll
            for (int u = 0; u < 4; u++) {
                split2u(rAf[u].x, rAf[u].y, h[2 * u],     l[2 * u]);
                split2u(rAf[u].z, rAf[u].w, h[2 * u + 1], l[2 * u + 1]);
            }
            *(uint4*)&Ah_s[am * SA + ahh]     = make_uint4(h[0], h[1], h[2], h[3]);
            *(uint4*)&Ah_s[am * SA + ahh + 8] = make_uint4(h[4], h[5], h[6], h[7]);
            *(uint4*)&Al_s[am * SA + ahh]     = make_uint4(l[0], l[1], l[2], l[3]);
            *(uint4*)&Al_s[am * SA + ahh + 8] = make_uint4(l[4], l[5], l[6], l[7]);
        } else {
            *(uint4*)&Ah_s[am * SA + ahh]     = rA_h[0];
            *(uint4*)&Ah_s[am * SA + ahh + 8] = rA_h[1];
            *(uint4*)&Al_s[am * SA + ahh]     = rA_l[0];
            *(uint4*)&Al_s[am * SA + ahh + 8] = rA_l[1];
        }
        #pragma unroll
        for (int p = 0; p < BPT; p++) {
            *(uint4*)&Bh_s[bn * SA + bo + p * 8] = rB_h[p];
            *(uint4*)&Bl_s[bn * SA + bo + p * 8] = rB_l[p];
        }
        __syncthreads();

        if (s < 15) {
            const int off = (s + 1) * 32;
            if (AFP32) {
                #pragma unroll
                for (int u = 0; u < 4; u++) rAf[u] = *(const float4*)(Af + off + u * 4);
            } else {
                rA_h[0] = *(const uint4*)(Ash + off); rA_h[1] = *(const uint4*)(Ash + off + 8);
                rA_l[0] = *(const uint4*)(Asl + off); rA_l[1] = *(const uint4*)(Asl + off + 8);
            }
            #pragma unroll
            for (int p = 0; p < BPT; p++) {
                rB_h[p] = *(const uint4*)(Bsh + off + p * 8);
                rB_l[p] = *(const uint4*)(Bsl + off + p * 8);
            }
        }

        const uint32_t base = smem_base + (uint32_t)(buf * BUF_H * 2);
        const uint32_t aBh = base;
        const uint32_t aBl = base + A_HALVES * 2;
        const uint32_t bBh = base + 2 * A_HALVES * 2;
        const uint32_t bBl = bBh + B_HALVES_T * 2;

        #pragma unroll
        for (int kk = 0; kk < 2; kk++) {
            const uint32_t ko = kk * 32;
            uint32_t Ah0[4], Ah1[4], Al0[4], Al1[4];
            uint32_t Bh[NB][4], Bl[NB][4];
            ldm_x4(Ah0, aBh + aoff0 + ko);
            ldm_x4(Ah1, aBh + aoff1 + ko);
            ldm_x4(Al0, aBl + aoff0 + ko);
            ldm_x4(Al1, aBl + aoff1 + ko);
            #pragma unroll
            for (int t = 0; t < NB; t++) {
                ldm_x4(Bh[t], bBh + boffs[t] + ko);
                ldm_x4(Bl[t], bBl + boffs[t] + ko);
            }

            #pragma unroll
            for (int i = 0; i < 2; i++) {
                uint32_t* ahp = i ? Ah1 : Ah0;
                uint32_t* alp = i ? Al1 : Al0;
                #pragma unroll
                for (int j = 0; j < NTILES; j++) {
                    uint32_t* bhp = Bh[j >> 1];
                    uint32_t* blp = Bl[j >> 1];
                    uint32_t bhf[2] = { bhp[(j & 1) * 2], bhp[(j & 1) * 2 + 1] };
                    uint32_t blf[2] = { blp[(j & 1) * 2], blp[(j & 1) * 2 + 1] };
                    mma_bf16(acc[i][j], ahp, bhf);
                    mma_bf16(acc[i][j], ahp, blf);
                    mma_bf16(acc[i][j], alp, bhf);
                }
            }
        }
    }

    #pragma unroll
    for (int i = 0; i < 2; i++) {
        #pragma unroll
        for (int j = 0; j < NTILES; j++) {
            int col_loc = warp_n + (j >> 1) * 16 + (j & 1) * 8 + 2 * t4;
            int cng = n0 + col_loc;
            float b0 = bias[cng], b1 = bias[cng + 1];
            int r0 = m0 + warp_m + i * 16 + g;
            int r1 = r0 + 8;
            float2 v0 = make_float2(acc[i][j][0] + b0, acc[i][j][1] + b1);
            float2 v1 = make_float2(acc[i][j][2] + b0, acc[i][j][3] + b1);
            if (HEADSPLIT) {
                int h = cng >> 6, dk = cng & 63;
                float* d0 = Y + ((size_t)((r0 >> 8) * H_ + h) * L_ + (r0 & 255)) * DK_ + dk;
                float* d1 = Y + ((size_t)((r1 >> 8) * H_ + h) * L_ + (r1 & 255)) * DK_ + dk;
                *(float2*)d0 = v0;
                *(float2*)d1 = v1;
            } else {
                *(float2*)(Y + (size_t)r0 * D_ + cng) = v0;
                *(float2*)(Y + (size_t)r1 * D_ + cng) = v1;
            }
        }
    }
}

// QKV: NT=128, fused fp32 split. grid (8, 4, 3), 96 CTAs per z-merged launch.
__global__ __launch_bounds__(256) void qkv_mma_kernel(
    const float* __restrict__ q, const float* __restrict__ k, const float* __restrict__ v,
    const float* __restrict__ bq, const float* __restrict__ bk, const float* __restrict__ bv)
{
    int z = blockIdx.z;
    const float* X    = (z == 0) ? q  : (z == 1 ? k  : v);
    const float* bias = (z == 0) ? bq : (z == 1 ? bk : bv);
    float* out        = (z == 0) ? g_qh : (z == 1 ? g_kh : g_vh);
    gemm_core<128, true, true>(X, nullptr, nullptr,
                               g_Whi + (size_t)z * (512*512), g_Wlo + (size_t)z * (512*512),
                               bias, out);
}

// Output projection: NT=64, bf16 ctx input. grid (8, 8) = 64 CTAs.
__global__ __launch_bounds__(256, 2) void out_mma_kernel(
    const float* __restrict__ b0, float* __restrict__ Y)
{
    gemm_core<64, false, false>(nullptr, g_ctx_hi, g_ctx_lo,
                                g_Whi + (size_t)3 * (512*512), g_Wlo + (size_t)3 * (512*512),
                                b0, Y);
}

// ---------------------------------------------------------------------------
// Scores: grid (8, 4, 32) = 1024 CTAs, 256 thr, smem ~26KB.
// i-tile 32, j-tile 64; thread = 2i x 4j. Writes E bf16 hi/lo + row partials.
// ---------------------------------------------------------------------------
#define SCQ_ST 34
#define SCK_ST 68

__global__ __launch_bounds__(256) void scores_kernel(
    const int* __restrict__ mask, const float* __restrict__ vp)
{
    __shared__ float Qs[64 * SCQ_ST];
    __shared__ float Ks[64 * SCK_ST];
    __shared__ float vps[64];

    const int tid = threadIdx.x;
    const int bh = blockIdx.z;
    const int b = bh >> 3, h = bh & 7;
    const int i0 = blockIdx.x * 32, j0 = blockIdx.y * 64;
    const int jb = blockIdx.y;

    const float* qh = g_qh + (size_t)(bh * L_ + i0) * DK_;
    const float* kh = g_kh + (size_t)(bh * L_ + j0) * DK_;

    if (tid < 64) vps[tid] = vp[h * DK_ + tid];
    {
        int r = tid >> 3, d0 = (tid & 7) * 8;
        float4 t0 = *(const float4*)&qh[(size_t)r * DK_ + d0];
        float4 t1 = *(const float4*)&qh[(size_t)r * DK_ + d0 + 4];
        Qs[(d0 + 0) * SCQ_ST + r] = t0.x; Qs[(d0 + 1) * SCQ_ST + r] = t0.y;
        Qs[(d0 + 2) * SCQ_ST + r] = t0.z; Qs[(d0 + 3) * SCQ_ST + r] = t0.w;
        Qs[(d0 + 4) * SCQ_ST + r] = t1.x; Qs[(d0 + 5) * SCQ_ST + r] = t1.y;
        Qs[(d0 + 6) * SCQ_ST + r] = t1.z; Qs[(d0 + 7) * SCQ_ST + r] = t1.w;
    }
    {
        int r = tid >> 2, d0 = (tid & 3) * 16;
        #pragma unroll
        for (int u = 0; u < 4; u++) {
            float4 t = *(const float4*)&kh[(size_t)r * DK_ + d0 + u * 4];
            Ks[(d0 + u * 4 + 0) * SCK_ST + r] = t.x;
            Ks[(d0 + u * 4 + 1) * SCK_ST + r] = t.y;
            Ks[(d0 + u * 4 + 2) * SCK_ST + r] = t.z;
            Ks[(d0 + u * 4 + 3) * SCK_ST + r] = t.w;
        }
    }
    __syncthreads();

    const int il2 = tid >> 4;
    const int jg  = tid & 15;

    float acc[2][4] = {};
    #pragma unroll 2
    for (int d = 0; d < 64; d++) {
        float w = vps[d];
        float2 qv = *(const float2*)&Qs[d * SCQ_ST + il2 * 2];
        float4 kv = *(const float4*)&Ks[d * SCK_ST + jg * 4];
        float qa[2] = {qv.x, qv.y};
        float kb[4] = {kv.x, kv.y, kv.z, kv.w};
        #pragma unroll
        for (int a = 0; a < 2; a++)
            #pragma unroll
            for (int c = 0; c < 4; c++)
                acc[a][c] += w * tanh_fast(qa[a] + kb[c]);
    }

    float rpart[2];
    #pragma unroll
    for (int a = 0; a < 2; a++) {
        int row = i0 + il2 * 2 + a;
        const int4 m = *(const int4*)(mask + ((size_t)b * L_ + row) * L_ + j0 + jg * 4);
        float e0 = m.x ? __expf(acc[a][0]) : 0.0f;
        float e1 = m.y ? __expf(acc[a][1]) : 0.0f;
        float e2 = m.z ? __expf(acc[a][2]) : 0.0f;
        float e3 = m.w ? __expf(acc[a][3]) : 0.0f;
        rpart[a] = (e0 + e1) + (e2 + e3);
        bf16 h0, l0, h1, l1, h2, l2, h3, l3;
        split_bf(e0, h0, l0); split_bf(e1, h1, l1);
        split_bf(e2, h2, l2); split_bf(e3, h3, l3);
        size_t off = (size_t)bh * (L_ * L_) + (size_t)row * L_ + j0 + jg * 4;
        bf162* ph = (bf162*)&g_Ehi[off];
        bf162* pl = (bf162*)&g_Elo[off];
        ph[0] = bf162(h0, h1); ph[1] = bf162(h2, h3);
        pl[0] = bf162(l0, l1); pl[1] = bf162(l2, l3);
    }
    #pragma unroll
    for (int a = 0; a < 2; a++) {
        #pragma unroll
        for (int off = 8; off > 0; off >>= 1)
            rpart[a] += __shfl_xor_sync(0xFFFFFFFFu, rpart[a], off);
    }
    if (jg == 0) {
        int row = i0 + il2 * 2;
        float* dst = g_rsum4 + ((size_t)(bh * 4 + jb)) * L_ + row;
        dst[0] = rpart[0];
        dst[1] = rpart[1];
    }
}

// ---------------------------------------------------------------------------
// PV via tensor cores: ctx[i][dk] = (1/rowsum) * sum_j E[i][j] * VT[dk][j]
// K=256 (8 stages). grid (2, 32) = 64 CTAs.
// ---------------------------------------------------------------------------
#define B_HALVES64 (64*SA)
#define PVBUF_H (2*A_HALVES + 2*B_HALVES64)

__global__ __launch_bounds__(256) void pv_mma_kernel()
{
    extern __shared__ __align__(16) bf16 smh[];
    const int tid = threadIdx.x;
    const int lane = tid & 31, wid = tid >> 5;
    const int g = lane >> 2, t4 = lane & 3;
    const int warp_m = (wid & 3) * 32;
    const int warp_n = (wid >> 2) * 32;
    const int m0 = blockIdx.x * 128;
    const int bhz = blockIdx.y;
    const int b = bhz >> 3, h = bhz & 7;

    const bf16* Ahi_g = g_Ehi + (size_t)bhz * (L_ * L_);
    const bf16* Alo_g = g_Elo + (size_t)bhz * (L_ * L_);
    const bf16* Bhi_g = g_VThi + (size_t)bhz * (DK_ * L_);
    const bf16* Blo_g = g_VTlo + (size_t)bhz * (DK_ * L_);

    const int am = tid >> 1, ah = (tid & 1) * 16;
    const int bn = tid >> 2, bo = (tid & 3) * 8;
    const bf16* Asrc_h = Ahi_g + (size_t)(m0 + am) * L_ + ah;
    const bf16* Asrc_l = Alo_g + (size_t)(m0 + am) * L_ + ah;
    const bf16* Bsrc_h = Bhi_g + (size_t)bn * L_ + bo;
    const bf16* Bsrc_l = Blo_g + (size_t)bn * L_ + bo;

    float acc[2][4][4];
    #pragma unroll
    for (int i = 0; i < 2; i++)
        #pragma unroll
        for (int j = 0; j < 4; j++)
            #pragma unroll
            for (int c = 0; c < 4; c++) acc[i][j][c] = 0.0f;

    const int lrow = lane & 15;
    const int lk   = (lane >> 4) * 8;
    const int bln  = lane & 7;
    const int bseg = (lane >> 3) & 1;
    const int bhi16 = (lane >> 4);
    const uint32_t smem_base = smem_u32(smh);
    const uint32_t aoff0 = ((warp_m + lrow)      * SA + lk) * 2;
    const uint32_t aoff1 = ((warp_m + 16 + lrow) * SA + lk) * 2;
    const uint32_t boff0 = ((warp_n + bln)       * SA + bseg * 8) * 2 + bhi16 * (8 * SA * 2);
    const uint32_t boff1 = boff0 + 16 * SA * 2;

    uint4 rAh0, rAh1, rAl0, rAl1, rBh, rBl;
    rAh0 = *(const uint4*)(Asrc_h);  rAh1 = *(const uint4*)(Asrc_h + 8);
    rAl0 = *(const uint4*)(Asrc_l);  rAl1 = *(const uint4*)(Asrc_l + 8);
    rBh  = *(const uint4*)(Bsrc_h);  rBl  = *(const uint4*)(Bsrc_l);

    for (int s = 0; s < 8; s++) {
        const int buf = s & 1;
        bf16* Ah_s = smh + buf * PVBUF_H;
        bf16* Al_s = Ah_s + A_HALVES;
        bf16* Bh_s = Al_s + A_HALVES;
        bf16* Bl_s = Bh_s + B_HALVES64;

        *(uint4*)&Ah_s[am * SA + ah]     = rAh0;
        *(uint4*)&Ah_s[am * SA + ah + 8] = rAh1;
        *(uint4*)&Al_s[am * SA + ah]     = rAl0;
        *(uint4*)&Al_s[am * SA + ah + 8] = rAl1;
        *(uint4*)&Bh_s[bn * SA + bo] = rBh;
        *(uint4*)&Bl_s[bn * SA + bo] = rBl;
        __syncthreads();

        if (s < 7) {
            const int off = (s + 1) * 32;
            rAh0 = *(const uint4*)(Asrc_h + off); rAh1 = *(const uint4*)(Asrc_h + off + 8);
            rAl0 = *(const uint4*)(Asrc_l + off); rAl1 = *(const uint4*)(Asrc_l + off + 8);
            rBh  = *(const uint4*)(Bsrc_h + off); rBl  = *(const uint4*)(Bsrc_l + off);
        }

        const uint32_t base = smem_base + (uint32_t)(buf * PVBUF_H * 2);
        const uint32_t aBh = base;
        const uint32_t aBl = base + A_HALVES * 2;
        const uint32_t bBh = base + 2 * A_HALVES * 2;
        const uint32_t bBl = bBh + B_HALVES64 * 2;

        #pragma unroll
        for (int kk = 0; kk < 2; kk++) {
            const uint32_t ko = kk * 32;
            uint32_t Ah0[4], Ah1[4], Al0[4], Al1[4];
            uint32_t Bh0[4], Bh1[4], Bl0[4], Bl1[4];
            ldm_x4(Ah0, aBh + aoff0 + ko);
            ldm_x4(Ah1, aBh + aoff1 + ko);
            ldm_x4(Al0, aBl + aoff0 + ko);
            ldm_x4(Al1, aBl + aoff1 + ko);
            ldm_x4(Bh0, bBh + boff0 + ko);
            ldm_x4(Bh1, bBh + boff1 + ko);
            ldm_x4(Bl0, bBl + boff0 + ko);
            ldm_x4(Bl1, bBl + boff1 + ko);

            #pragma unroll
            for (int i = 0; i < 2; i++) {
                uint32_t* ahp = i ? Ah1 : Ah0;
                uint32_t* alp = i ? Al1 : Al0;
                #pragma unroll
                for (int j = 0; j < 4; j++) {
                    uint32_t* bhp = (j < 2) ? Bh0 : Bh1;
                    uint32_t* blp = (j < 2) ? Bl0 : Bl1;
                    uint32_t bhf[2] = { bhp[(j & 1) * 2], bhp[(j & 1) * 2 + 1] };
                    uint32_t blf[2] = { blp[(j & 1) * 2], blp[(j & 1) * 2 + 1] };
                    mma_bf16(acc[i][j], ahp, bhf);
                    mma_bf16(acc[i][j], ahp, blf);
                    mma_bf16(acc[i][j], alp, bhf);
                }
            }
        }
    }

    const float* rs = g_rsum4 + (size_t)(bhz * 4) * L_;
    #pragma unroll
    for (int i = 0; i < 2; i++) {
        #pragma unroll
        for (int j = 0; j < 4; j++) {
            int col_loc = warp_n + (j >> 1) * 16 + (j & 1) * 8 + 2 * t4;
            int r0 = m0 + warp_m + i * 16 + g;
            int r1 = r0 + 8;
            float inv0 = 1.0f / ((rs[r0] + rs[L_ + r0]) + (rs[2 * L_ + r0] + rs[3 * L_ + r0]));
            float inv1 = 1.0f / ((rs[r1] + rs[L_ + r1]) + (rs[2 * L_ + r1] + rs[3 * L_ + r1]));
            float v00 = acc[i][j][0] * inv0, v01 = acc[i][j][1] * inv0;
            float v10 = acc[i][j][2] * inv1, v11 = acc[i][j][3] * inv1;
            bf16 ha, la, hb, lb;
            size_t o0 = ((size_t)(b * L_ + r0)) * D_ + h * DK_ + col_loc;
            size_t o1 = ((size_t)(b * L_ + r1)) * D_ + h * DK_ + col_loc;
            split_bf(v00, ha, la); split_bf(v01, hb, lb);
            *(bf162*)&g_ctx_hi[o0] = bf162(ha, hb);
            *(bf162*)&g_ctx_lo[o0] = bf162(la, lb);
            split_bf(v10, ha, la); split_bf(v11, hb, lb);
            *(bf162*)&g_ctx_hi[o1] = bf162(ha, hb);
            *(bf162*)&g_ctx_lo[o1] = bf162(la, lb);
        }
    }
}

// ===========================================================================
extern "C" void kernel_launch(void* const* d_in, const int* in_sizes, int n_in,
                              void* d_out, int out_size)
{
    const float* q    = (const float*)d_in[0];
    const float* k    = (const float*)d_in[1];
    const float* v    = (const float*)d_in[2];
    const int*   mask = (const int*)  d_in[3];
    const float* Wq   = (const float*)d_in[4];
    const float* bq   = (const float*)d_in[5];
    const float* Wk   = (const float*)d_in[6];
    const float* bk   = (const float*)d_in[7];
    const float* Wv   = (const float*)d_in[8];
    const float* bv   = (const float*)d_in[9];
    const float* vp   = (const float*)d_in[10];
    const float* W0   = (const float*)d_in[11];
    const float* b0   = (const float*)d_in[12];
    float* out = (float*)d_out;

    static bool attr_set = false;
    if (!attr_set) {
        cudaFuncSetAttribute(qkv_mma_kernel,
                             cudaFuncAttributeMaxDynamicSharedMemorySize, gemm_smem_b(128));
        cudaFuncSetAttribute(out_mma_kernel,
                             cudaFuncAttributeMaxDynamicSharedMemorySize, gemm_smem_b(64));
        cudaFuncSetAttribute(pv_mma_kernel,
                             cudaFuncAttributeMaxDynamicSharedMemorySize, gemm_smem_b(64));
        attr_set = true;
    }

    convert_w_kernel<<<dim3(16, 16, 4), dim3(32, 8)>>>(Wq, Wk, Wv, W0);
    qkv_mma_kernel<<<dim3(8, 4, 3), 256, gemm_smem_b(128)>>>(q, k, v, bq, bk, bv);
    convert_vT_kernel<<<dim3(8, 2, 32), dim3(32, 8)>>>();
    scores_kernel<<<dim3(8, 4, 32), 256>>>(mask, vp);
    pv_mma_kernel<<<dim3(2, 32), 256, gemm_smem_b(64)>>>();
    out_mma_kernel<<<dim3(8, 8), 256, gemm_smem_b(64)>>>(b0, out);
}